// round 1
// baseline (speedup 1.0000x reference)
#include <cuda_runtime.h>
#include <math.h>

#define NN 50000
#define NE 800000
#define NHEADS 4
#define SLOPE 0.2f

// ---------------- scratch (static device globals; no allocation) ----------------
__device__ float g_proj1[NN * 400];   // 80 MB
__device__ float g_h1[NN * 400];      // 80 MB
__device__ float g_proj2[NN * 512];   // 102.4 MB
__device__ float g_el1[NN * NHEADS];
__device__ float g_er1[NN * NHEADS];
__device__ float g_el2[NN * NHEADS];
__device__ float g_er2[NN * NHEADS];
__device__ int   g_deg[NN];
__device__ int   g_rowptr[NN + 1];
__device__ int   g_cursor[NN];
__device__ int   g_srcs[NE];          // src ids sorted by dst (CSR payload)

__device__ __forceinline__ float lrelu(float x) { return x > 0.f ? x : SLOPE * x; }

// ---------------- SGEMM: C[M,N] = A[M,K] @ B[K,N], fp32 ----------------
#define BM 128
#define BN 64
#define BK 16
#define TM 8
#define TN 4

__global__ void sgemm_kernel(const float* __restrict__ A, const float* __restrict__ B,
                             float* __restrict__ C, int M, int N, int K) {
    __shared__ float As[BK][BM + 4];
    __shared__ float Bs[BK][BN];
    const int tid = threadIdx.x;
    const int tx = tid & 15;        // 0..15  (N dim)
    const int ty = tid >> 4;        // 0..15  (M dim)
    const int bm = blockIdx.y * BM;
    const int bn = blockIdx.x * BN;

    float acc[TM][TN];
#pragma unroll
    for (int i = 0; i < TM; i++)
#pragma unroll
        for (int j = 0; j < TN; j++) acc[i][j] = 0.f;

    for (int kt = 0; kt < K; kt += BK) {
        // load A tile (BM x BK), store transposed
        for (int l = tid; l < BM * BK; l += 256) {
            int r = l >> 4;          // 0..127
            int c = l & 15;          // 0..15
            int gr = bm + r, gc = kt + c;
            float v = 0.f;
            if (gr < M && gc < K) v = A[(size_t)gr * K + gc];
            As[c][r] = v;
        }
        // load B tile (BK x BN)
        for (int l = tid; l < BK * BN; l += 256) {
            int r = l >> 6;          // 0..15
            int c = l & 63;          // 0..63
            int gr = kt + r, gc = bn + c;
            float v = 0.f;
            if (gr < K && gc < N) v = B[(size_t)gr * N + gc];
            Bs[r][c] = v;
        }
        __syncthreads();
#pragma unroll
        for (int k = 0; k < BK; k++) {
            float a[TM], b[TN];
#pragma unroll
            for (int i = 0; i < TM; i++) a[i] = As[k][ty * TM + i];
#pragma unroll
            for (int j = 0; j < TN; j++) b[j] = Bs[k][tx * TN + j];
#pragma unroll
            for (int i = 0; i < TM; i++)
#pragma unroll
                for (int j = 0; j < TN; j++)
                    acc[i][j] = fmaf(a[i], b[j], acc[i][j]);
        }
        __syncthreads();
    }

#pragma unroll
    for (int i = 0; i < TM; i++) {
        int gr = bm + ty * TM + i;
        if (gr >= M) continue;
#pragma unroll
        for (int j = 0; j < TN; j++) {
            int gc = bn + tx * TN + j;
            if (gc < N) C[(size_t)gr * N + gc] = acc[i][j];
        }
    }
}

// ---------------- attention scores: el[n,h]=<proj[n,h,:],al[h,:]> ----------------
template <int DH>
__global__ void scores_kernel(const float* __restrict__ proj,
                              const float* __restrict__ al, const float* __restrict__ ar,
                              float* __restrict__ el, float* __restrict__ er) {
    const int n = blockIdx.x;
    const int h = threadIdx.x >> 5;     // 4 warps = 4 heads
    const int lane = threadIdx.x & 31;
    const float* p = proj + (size_t)n * (4 * DH) + h * DH;
    float sl = 0.f, sr = 0.f;
    for (int c = lane; c < DH; c += 32) {
        float pv = p[c];
        sl = fmaf(pv, al[h * DH + c], sl);
        sr = fmaf(pv, ar[h * DH + c], sr);
    }
#pragma unroll
    for (int o = 16; o; o >>= 1) {
        sl += __shfl_down_sync(0xffffffffu, sl, o);
        sr += __shfl_down_sync(0xffffffffu, sr, o);
    }
    if (lane == 0) {
        el[n * 4 + h] = sl;
        er[n * 4 + h] = sr;
    }
}

// ---------------- CSR build ----------------
__global__ void zero_deg_kernel() {
    int i = blockIdx.x * blockDim.x + threadIdx.x;
    if (i < NN) g_deg[i] = 0;
}

__global__ void count_deg_kernel(const int* __restrict__ dst) {
    int e = blockIdx.x * blockDim.x + threadIdx.x;
    if (e < NE) atomicAdd(&g_deg[dst[e]], 1);
}

__global__ void scan_kernel() {
    __shared__ int sh[1024];
    const int t = threadIdx.x;
    const int CHUNK = (NN + 1023) / 1024;   // 49
    int beg = t * CHUNK;
    int end = min(beg + CHUNK, NN);
    int s = 0;
    for (int i = beg; i < end; i++) s += g_deg[i];
    sh[t] = s;
    __syncthreads();
    for (int off = 1; off < 1024; off <<= 1) {
        int v = (t >= off) ? sh[t - off] : 0;
        __syncthreads();
        sh[t] += v;
        __syncthreads();
    }
    int run = t ? sh[t - 1] : 0;
    for (int i = beg; i < end; i++) {
        g_rowptr[i] = run;
        g_cursor[i] = run;
        run += g_deg[i];
    }
    if (t == 0) g_rowptr[NN] = sh[1023];
}

__global__ void scatter_kernel(const int* __restrict__ src, const int* __restrict__ dst) {
    int e = blockIdx.x * blockDim.x + threadIdx.x;
    if (e < NE) {
        int p = atomicAdd(&g_cursor[dst[e]], 1);
        g_srcs[p] = src[e];
    }
}

// ---------------- per-dst softmax-weighted aggregation ----------------
// one block (128 threads) per dst node; accumulators in registers.
template <int DH, bool ACT>
__global__ void aggregate_kernel(const float* __restrict__ proj,
                                 const float* __restrict__ el, const float* __restrict__ er,
                                 const float* __restrict__ bias, float* __restrict__ out) {
    const int CH = 4 * DH;
    const int d = blockIdx.x;
    const int t = threadIdx.x;
    const int beg = g_rowptr[d];
    const int end = g_rowptr[d + 1];

    const float4 erd = reinterpret_cast<const float4*>(er)[d];

    // phase 1: per-head running max (computed redundantly by every thread)
    float m0 = -1e30f, m1 = -1e30f, m2 = -1e30f, m3 = -1e30f;
    for (int e = beg; e < end; e++) {
        int sn = g_srcs[e];
        float4 l = reinterpret_cast<const float4*>(el)[sn];
        m0 = fmaxf(m0, lrelu(l.x + erd.x));
        m1 = fmaxf(m1, lrelu(l.y + erd.y));
        m2 = fmaxf(m2, lrelu(l.z + erd.z));
        m3 = fmaxf(m3, lrelu(l.w + erd.w));
    }

    // per-thread channel -> head map
    int hd[4];
#pragma unroll
    for (int i = 0; i < 4; i++) {
        int c = t + 128 * i;
        hd[i] = (c < CH) ? (c / DH) : 0;
    }

    // phase 2: accumulate exp-weighted messages
    float acc[4] = {0.f, 0.f, 0.f, 0.f};
    float s0 = 0.f, s1 = 0.f, s2 = 0.f, s3 = 0.f;
    for (int e = beg; e < end; e++) {
        int sn = g_srcs[e];
        float4 l = reinterpret_cast<const float4*>(el)[sn];
        float ex[4];
        ex[0] = __expf(lrelu(l.x + erd.x) - m0); s0 += ex[0];
        ex[1] = __expf(lrelu(l.y + erd.y) - m1); s1 += ex[1];
        ex[2] = __expf(lrelu(l.z + erd.z) - m2); s2 += ex[2];
        ex[3] = __expf(lrelu(l.w + erd.w) - m3); s3 += ex[3];
        const float* pr = proj + (size_t)sn * CH;
#pragma unroll
        for (int i = 0; i < 4; i++) {
            int c = t + 128 * i;
            if (c < CH) acc[i] = fmaf(ex[hd[i]], pr[c], acc[i]);
        }
    }

    float sums[4] = {s0 + 1e-9f, s1 + 1e-9f, s2 + 1e-9f, s3 + 1e-9f};
#pragma unroll
    for (int i = 0; i < 4; i++) {
        int c = t + 128 * i;
        if (c < CH) {
            float v = acc[i] / sums[hd[i]] + bias[c];
            if (ACT) v = lrelu(v);
            out[(size_t)d * CH + c] = v;
        }
    }
}

// ---------------- launch ----------------
extern "C" void kernel_launch(void* const* d_in, const int* in_sizes, int n_in,
                              void* d_out, int out_size) {
    const float* x   = (const float*)d_in[0];
    const float* W1  = (const float*)d_in[1];
    const float* al1 = (const float*)d_in[2];
    const float* ar1 = (const float*)d_in[3];
    const float* b1  = (const float*)d_in[4];
    const float* W2  = (const float*)d_in[5];
    const float* al2 = (const float*)d_in[6];
    const float* ar2 = (const float*)d_in[7];
    const float* b2  = (const float*)d_in[8];
    const int*   src = (const int*)d_in[9];
    const int*   dst = (const int*)d_in[10];
    float* out = (float*)d_out;

    float *proj1, *h1, *proj2, *el1, *er1, *el2, *er2;
    cudaGetSymbolAddress((void**)&proj1, g_proj1);
    cudaGetSymbolAddress((void**)&h1, g_h1);
    cudaGetSymbolAddress((void**)&proj2, g_proj2);
    cudaGetSymbolAddress((void**)&el1, g_el1);
    cudaGetSymbolAddress((void**)&er1, g_er1);
    cudaGetSymbolAddress((void**)&el2, g_el2);
    cudaGetSymbolAddress((void**)&er2, g_er2);

    // CSR build (shared by both layers)
    zero_deg_kernel<<<(NN + 255) / 256, 256>>>();
    count_deg_kernel<<<(NE + 255) / 256, 256>>>(dst);
    scan_kernel<<<1, 1024>>>();
    scatter_kernel<<<(NE + 255) / 256, 256>>>(src, dst);

    // layer 1
    {
        dim3 grid((400 + BN - 1) / BN, (NN + BM - 1) / BM);
        sgemm_kernel<<<grid, 256>>>(x, W1, proj1, NN, 400, 300);
    }
    scores_kernel<100><<<NN, 128>>>(proj1, al1, ar1, el1, er1);
    aggregate_kernel<100, true><<<NN, 128>>>(proj1, el1, er1, b1, h1);

    // layer 2
    {
        dim3 grid((512 + BN - 1) / BN, (NN + BM - 1) / BM);
        sgemm_kernel<<<grid, 256>>>(h1, W2, proj2, NN, 512, 400);
    }
    scores_kernel<128><<<NN, 128>>>(proj2, al2, ar2, el2, er2);
    aggregate_kernel<128, false><<<NN, 128>>>(proj2, el2, er2, b2, out);
}

// round 2
// speedup vs baseline: 1.3967x; 1.3967x over previous
#include <cuda_runtime.h>
#include <mma.h>
#include <math.h>

using namespace nvcuda;

#define NN 50000
#define NE 800000
#define NHEADS 4
#define SLOPE 0.2f

// ---------------- scratch (static device globals; no allocation) ----------------
__device__ float g_proj1[NN * 400];   // 80 MB
__device__ float g_h1[NN * 400];      // 80 MB
__device__ float g_proj2[NN * 512];   // 102.4 MB
__device__ float g_el1[NN * NHEADS];
__device__ float g_er1[NN * NHEADS];
__device__ float g_el2[NN * NHEADS];
__device__ float g_er2[NN * NHEADS];
__device__ int   g_deg[NN];
__device__ int   g_rowptr[NN + 1];
__device__ int   g_cursor[NN];
__device__ int   g_srcs[NE];          // src ids sorted by dst (CSR payload)

__device__ __forceinline__ float lrelu(float x) { return x > 0.f ? x : SLOPE * x; }

// ---------------- TF32 WMMA GEMM: C[M,N] = A[M,K] @ B[K,N] ----------------
// block tile 128x64x16, 8 warps (4x2), warp tile 32x32 (2x2 wmma m16n16k8)
#define GBM 128
#define GBN 64
#define GBK 16
#define LDA 24          // padded BM-row stride for As (mult of 4 -> float4 aligned)
#define LDB 68          // padded Bs row stride
#define LDC 68          // staging row stride
#define SBUF_FLOATS 8704  // max(128*24 + 16*68 = 4160, 128*68 = 8704)

__global__ void __launch_bounds__(256, 2)
gemm_tf32_kernel(const float* __restrict__ A, const float* __restrict__ B,
                 float* __restrict__ C, int M, int N, int K) {
    __shared__ float sbuf[SBUF_FLOATS];
    float* As = sbuf;                  // [128][LDA]
    float* Bs = sbuf + GBM * LDA;      // [16][LDB]

    const int tid = threadIdx.x;
    const int warp = tid >> 5;
    const int wm = warp & 3;           // 0..3 -> M offset wm*32
    const int wn = warp >> 2;          // 0..1 -> N offset wn*32
    const int bm = blockIdx.y * GBM;
    const int bn = blockIdx.x * GBN;

    wmma::fragment<wmma::accumulator, 16, 16, 8, float> acc[2][2];
#pragma unroll
    for (int i = 0; i < 2; i++)
#pragma unroll
        for (int j = 0; j < 2; j++) wmma::fill_fragment(acc[i][j], 0.f);

    for (int kt = 0; kt < K; kt += GBK) {
        const bool kfull = (kt + GBK) <= K;
        // ---- load A tile: 128 rows x 16 cols = 512 float4 slots, 2 per thread
#pragma unroll
        for (int it = 0; it < 2; it++) {
            int s = tid + 256 * it;
            int r = s >> 2;            // 0..127
            int c4 = s & 3;            // 0..3
            int gr = bm + r, gc = kt + c4 * 4;
            float4 v = make_float4(0.f, 0.f, 0.f, 0.f);
            if (gr < M) {
                if (kfull) {
                    v = *reinterpret_cast<const float4*>(A + (size_t)gr * K + gc);
                } else {
                    const float* ap = A + (size_t)gr * K;
                    if (gc + 0 < K) v.x = ap[gc + 0];
                    if (gc + 1 < K) v.y = ap[gc + 1];
                    if (gc + 2 < K) v.z = ap[gc + 2];
                    if (gc + 3 < K) v.w = ap[gc + 3];
                }
            }
            *reinterpret_cast<float4*>(&As[r * LDA + c4 * 4]) = v;
        }
        // ---- load B tile: 16 rows x 64 cols = 256 float4 slots, 1 per thread
        {
            int r = tid >> 4;          // 0..15
            int c4 = tid & 15;         // 0..15
            int gr = kt + r, gc = bn + c4 * 4;
            float4 v = make_float4(0.f, 0.f, 0.f, 0.f);
            if (gr < K && gc < N)
                v = *reinterpret_cast<const float4*>(B + (size_t)gr * N + gc);
            *reinterpret_cast<float4*>(&Bs[r * LDB + c4 * 4]) = v;
        }
        __syncthreads();

#pragma unroll
        for (int ks = 0; ks < GBK; ks += 8) {
            wmma::fragment<wmma::matrix_a, 16, 16, 8, wmma::precision::tf32, wmma::row_major> af[2];
            wmma::fragment<wmma::matrix_b, 16, 16, 8, wmma::precision::tf32, wmma::row_major> bf[2];
#pragma unroll
            for (int i = 0; i < 2; i++) {
                wmma::load_matrix_sync(af[i], &As[(wm * 32 + i * 16) * LDA + ks], LDA);
#pragma unroll
                for (int t = 0; t < af[i].num_elements; t++)
                    af[i].x[t] = wmma::__float_to_tf32(af[i].x[t]);
            }
#pragma unroll
            for (int j = 0; j < 2; j++) {
                wmma::load_matrix_sync(bf[j], &Bs[ks * LDB + wn * 32 + j * 16], LDB);
#pragma unroll
                for (int t = 0; t < bf[j].num_elements; t++)
                    bf[j].x[t] = wmma::__float_to_tf32(bf[j].x[t]);
            }
#pragma unroll
            for (int i = 0; i < 2; i++)
#pragma unroll
                for (int j = 0; j < 2; j++)
                    wmma::mma_sync(acc[i][j], af[i], bf[j], acc[i][j]);
        }
        __syncthreads();
    }

    // ---- epilogue: stage through smem, then guarded float4 stores
    float* CS = sbuf;  // [128][LDC]
#pragma unroll
    for (int i = 0; i < 2; i++)
#pragma unroll
        for (int j = 0; j < 2; j++)
            wmma::store_matrix_sync(&CS[(wm * 32 + i * 16) * LDC + wn * 32 + j * 16],
                                    acc[i][j], LDC, wmma::mem_row_major);
    __syncthreads();

#pragma unroll
    for (int it = 0; it < 8; it++) {
        int s = tid + 256 * it;        // 0..2047 float4 slots
        int r = s >> 4;                // 0..127
        int c4 = s & 15;               // 0..15
        int gr = bm + r, gc = bn + c4 * 4;
        if (gr < M && gc < N) {
            float4 v = *reinterpret_cast<float4*>(&CS[r * LDC + c4 * 4]);
            *reinterpret_cast<float4*>(C + (size_t)gr * N + gc) = v;
        }
    }
}

// ---------------- attention scores: el[n,h]=<proj[n,h,:],al[h,:]> ----------------
template <int DH>
__global__ void scores_kernel(const float* __restrict__ proj,
                              const float* __restrict__ al, const float* __restrict__ ar,
                              float* __restrict__ el, float* __restrict__ er) {
    const int n = blockIdx.x;
    const int h = threadIdx.x >> 5;     // 4 warps = 4 heads
    const int lane = threadIdx.x & 31;
    const float* p = proj + (size_t)n * (4 * DH) + h * DH;
    float sl = 0.f, sr = 0.f;
    for (int c = lane; c < DH; c += 32) {
        float pv = p[c];
        sl = fmaf(pv, al[h * DH + c], sl);
        sr = fmaf(pv, ar[h * DH + c], sr);
    }
#pragma unroll
    for (int o = 16; o; o >>= 1) {
        sl += __shfl_down_sync(0xffffffffu, sl, o);
        sr += __shfl_down_sync(0xffffffffu, sr, o);
    }
    if (lane == 0) {
        el[n * 4 + h] = sl;
        er[n * 4 + h] = sr;
    }
}

// ---------------- CSR build ----------------
__global__ void zero_deg_kernel() {
    int i = blockIdx.x * blockDim.x + threadIdx.x;
    if (i < NN) g_deg[i] = 0;
}

__global__ void count_deg_kernel(const int* __restrict__ dst) {
    int e = blockIdx.x * blockDim.x + threadIdx.x;
    if (e < NE) atomicAdd(&g_deg[dst[e]], 1);
}

__global__ void scan_kernel() {
    __shared__ int sh[1024];
    const int t = threadIdx.x;
    const int CHUNK = (NN + 1023) / 1024;   // 49
    int beg = t * CHUNK;
    int end = min(beg + CHUNK, NN);
    int s = 0;
    for (int i = beg; i < end; i++) s += g_deg[i];
    sh[t] = s;
    __syncthreads();
    for (int off = 1; off < 1024; off <<= 1) {
        int v = (t >= off) ? sh[t - off] : 0;
        __syncthreads();
        sh[t] += v;
        __syncthreads();
    }
    int run = t ? sh[t - 1] : 0;
    for (int i = beg; i < end; i++) {
        g_rowptr[i] = run;
        g_cursor[i] = run;
        run += g_deg[i];
    }
    if (t == 0) g_rowptr[NN] = sh[1023];
}

__global__ void scatter_kernel(const int* __restrict__ src, const int* __restrict__ dst) {
    int e = blockIdx.x * blockDim.x + threadIdx.x;
    if (e < NE) {
        int p = atomicAdd(&g_cursor[dst[e]], 1);
        g_srcs[p] = src[e];
    }
}

// ---------------- per-dst softmax-weighted aggregation ----------------
// one block (128 threads) per dst node; accumulators in registers.
template <int DH, bool ACT>
__global__ void aggregate_kernel(const float* __restrict__ proj,
                                 const float* __restrict__ el, const float* __restrict__ er,
                                 const float* __restrict__ bias, float* __restrict__ out) {
    const int CH = 4 * DH;
    const int d = blockIdx.x;
    const int t = threadIdx.x;
    const int beg = g_rowptr[d];
    const int end = g_rowptr[d + 1];

    const float4 erd = reinterpret_cast<const float4*>(er)[d];

    // phase 1: per-head running max (computed redundantly by every thread)
    float m0 = -1e30f, m1 = -1e30f, m2 = -1e30f, m3 = -1e30f;
    for (int e = beg; e < end; e++) {
        int sn = g_srcs[e];
        float4 l = reinterpret_cast<const float4*>(el)[sn];
        m0 = fmaxf(m0, lrelu(l.x + erd.x));
        m1 = fmaxf(m1, lrelu(l.y + erd.y));
        m2 = fmaxf(m2, lrelu(l.z + erd.z));
        m3 = fmaxf(m3, lrelu(l.w + erd.w));
    }

    // per-thread channel -> head map
    int hd[4];
#pragma unroll
    for (int i = 0; i < 4; i++) {
        int c = t + 128 * i;
        hd[i] = (c < CH) ? (c / DH) : 0;
    }

    // phase 2: accumulate exp-weighted messages
    float acc[4] = {0.f, 0.f, 0.f, 0.f};
    float s0 = 0.f, s1 = 0.f, s2 = 0.f, s3 = 0.f;
    for (int e = beg; e < end; e++) {
        int sn = g_srcs[e];
        float4 l = reinterpret_cast<const float4*>(el)[sn];
        float ex[4];
        ex[0] = __expf(lrelu(l.x + erd.x) - m0); s0 += ex[0];
        ex[1] = __expf(lrelu(l.y + erd.y) - m1); s1 += ex[1];
        ex[2] = __expf(lrelu(l.z + erd.z) - m2); s2 += ex[2];
        ex[3] = __expf(lrelu(l.w + erd.w) - m3); s3 += ex[3];
        const float* pr = proj + (size_t)sn * CH;
#pragma unroll
        for (int i = 0; i < 4; i++) {
            int c = t + 128 * i;
            if (c < CH) acc[i] = fmaf(ex[hd[i]], pr[c], acc[i]);
        }
    }

    float sums[4] = {s0 + 1e-9f, s1 + 1e-9f, s2 + 1e-9f, s3 + 1e-9f};
#pragma unroll
    for (int i = 0; i < 4; i++) {
        int c = t + 128 * i;
        if (c < CH) {
            float v = acc[i] / sums[hd[i]] + bias[c];
            if (ACT) v = lrelu(v);
            out[(size_t)d * CH + c] = v;
        }
    }
}

// ---------------- launch ----------------
extern "C" void kernel_launch(void* const* d_in, const int* in_sizes, int n_in,
                              void* d_out, int out_size) {
    const float* x   = (const float*)d_in[0];
    const float* W1  = (const float*)d_in[1];
    const float* al1 = (const float*)d_in[2];
    const float* ar1 = (const float*)d_in[3];
    const float* b1  = (const float*)d_in[4];
    const float* W2  = (const float*)d_in[5];
    const float* al2 = (const float*)d_in[6];
    const float* ar2 = (const float*)d_in[7];
    const float* b2  = (const float*)d_in[8];
    const int*   src = (const int*)d_in[9];
    const int*   dst = (const int*)d_in[10];
    float* out = (float*)d_out;

    float *proj1, *h1, *proj2, *el1, *er1, *el2, *er2;
    cudaGetSymbolAddress((void**)&proj1, g_proj1);
    cudaGetSymbolAddress((void**)&h1, g_h1);
    cudaGetSymbolAddress((void**)&proj2, g_proj2);
    cudaGetSymbolAddress((void**)&el1, g_el1);
    cudaGetSymbolAddress((void**)&er1, g_er1);
    cudaGetSymbolAddress((void**)&el2, g_el2);
    cudaGetSymbolAddress((void**)&er2, g_er2);

    // CSR build (shared by both layers)
    zero_deg_kernel<<<(NN + 255) / 256, 256>>>();
    count_deg_kernel<<<(NE + 255) / 256, 256>>>(dst);
    scan_kernel<<<1, 1024>>>();
    scatter_kernel<<<(NE + 255) / 256, 256>>>(src, dst);

    // layer 1
    {
        dim3 grid((400 + GBN - 1) / GBN, (NN + GBM - 1) / GBM);
        gemm_tf32_kernel<<<grid, 256>>>(x, W1, proj1, NN, 400, 300);
    }
    scores_kernel<100><<<NN, 128>>>(proj1, al1, ar1, el1, er1);
    aggregate_kernel<100, true><<<NN, 128>>>(proj1, el1, er1, b1, h1);

    // layer 2
    {
        dim3 grid((512 + GBN - 1) / GBN, (NN + GBM - 1) / GBM);
        gemm_tf32_kernel<<<grid, 256>>>(h1, W2, proj2, NN, 512, 400);
    }
    scores_kernel<128><<<NN, 128>>>(proj2, al2, ar2, el2, er2);
    aggregate_kernel<128, false><<<NN, 128>>>(proj2, el2, er2, b2, out);
}

// round 3
// speedup vs baseline: 1.5555x; 1.1137x over previous
#include <cuda_runtime.h>
#include <mma.h>
#include <math.h>

using namespace nvcuda;

#define NN 50000
#define NE 800000
#define NHEADS 4
#define SLOPE 0.2f

// ---------------- scratch (static device globals; no allocation) ----------------
__device__ float g_proj1[NN * 400];   // 80 MB
__device__ float g_h1[NN * 400];      // 80 MB
__device__ float g_proj2[NN * 512];   // 102.4 MB
__device__ float g_el1[NN * NHEADS];
__device__ float g_er1[NN * NHEADS];
__device__ float g_el2[NN * NHEADS];
__device__ float g_er2[NN * NHEADS];
__device__ int   g_deg[NN];
__device__ int   g_rowptr[NN + 1];
__device__ int   g_cursor[NN];
__device__ int   g_srcs[NE];          // src ids sorted by dst (CSR payload)

__device__ __forceinline__ float lrelu(float x) { return x > 0.f ? x : SLOPE * x; }

// ---------------- cp.async helpers ----------------
__device__ __forceinline__ void cp_async16(void* smem, const void* g) {
    unsigned saddr = (unsigned)__cvta_generic_to_shared(smem);
    asm volatile("cp.async.cg.shared.global [%0], [%1], 16;\n" :: "r"(saddr), "l"(g));
}
__device__ __forceinline__ void cp_commit() { asm volatile("cp.async.commit_group;\n" ::: "memory"); }
__device__ __forceinline__ void cp_wait0()  { asm volatile("cp.async.wait_group 0;\n" ::: "memory"); }

// ---------------- TF32 WMMA GEMM, double-buffered cp.async pipeline ----------------
// Block tile 128 x GBN x 16. 8 warps: 2 (M, x64) x 4 (N, x GBN/4).
// Warp tile 64 x (GBN/4): 4 x WN fragments of m16n16k8.
#define GBM 128
#define GBK 16
#define LDA 20   // padded row stride for As tile (floats)

template <int GBN_T>
__global__ void __launch_bounds__(256, 2)
gemm_tf32_db(const float* __restrict__ A, const float* __restrict__ B,
             float* __restrict__ C, int M, int N, int K) {
    constexpr int LDB  = GBN_T + 4;
    constexpr int WN   = GBN_T / 64;           // frags per warp in N (1 or 2)
    constexpr int WNT  = WN * 16;              // warp N-tile width
    constexpr int ABUF = GBM * LDA;            // 2560
    constexpr int BBUF = GBK * LDB;
    constexpr int TILEBUF = ABUF + BBUF;
    constexpr int STAGE   = 64 * LDB;          // half-epilogue staging
    constexpr int SMEMF   = (2 * TILEBUF > STAGE) ? 2 * TILEBUF : STAGE;

    __shared__ float sbuf[SMEMF];

    const int tid  = threadIdx.x;
    const int warp = tid >> 5;
    const int wm   = warp & 1;                 // M: 0..1 (x64)
    const int wn   = warp >> 1;                // N: 0..3 (x WNT)
    const int bm   = blockIdx.y * GBM;
    const int bn   = blockIdx.x * GBN_T;

    wmma::fragment<wmma::accumulator, 16, 16, 8, float> acc[4][WN];
#pragma unroll
    for (int i = 0; i < 4; i++)
#pragma unroll
        for (int j = 0; j < WN; j++) wmma::fill_fragment(acc[i][j], 0.f);

    // tile loader: all-float4 slots, each fully valid (cp.async) or zeroed
    auto load_tile = [&](int buf, int kt) {
        float* As = sbuf + buf * TILEBUF;
        float* Bs = As + ABUF;
        // A: 128 x 16 -> 512 float4 slots
#pragma unroll
        for (int it = 0; it < 2; it++) {
            int s = tid + 256 * it;
            int r = s >> 2, c4 = s & 3;
            int gr = bm + r, gc = kt + c4 * 4;
            float* dstp = &As[r * LDA + c4 * 4];
            if (gr < M && gc < K) cp_async16(dstp, A + (size_t)gr * K + gc);
            else *reinterpret_cast<float4*>(dstp) = make_float4(0.f, 0.f, 0.f, 0.f);
        }
        // B: 16 x GBN -> GBN*4 float4 slots
        constexpr int BS = GBK * GBN_T / 4;
#pragma unroll
        for (int s = 0; s < BS; s += 256) {
            int sl = s + tid;
            int r = sl / (GBN_T / 4), c4 = sl % (GBN_T / 4);
            int gr = kt + r, gc = bn + c4 * 4;
            float* dstp = &Bs[r * LDB + c4 * 4];
            if (gr < K && gc < N) cp_async16(dstp, B + (size_t)gr * N + gc);
            else *reinterpret_cast<float4*>(dstp) = make_float4(0.f, 0.f, 0.f, 0.f);
        }
        cp_commit();
    };

    load_tile(0, 0);

    int buf = 0;
    for (int kt = 0; kt < K; kt += GBK) {
        cp_wait0();
        __syncthreads();
        if (kt + GBK < K) load_tile(buf ^ 1, kt + GBK);

        const float* As = sbuf + buf * TILEBUF;
        const float* Bs = As + ABUF;
#pragma unroll
        for (int ks = 0; ks < GBK; ks += 8) {
            wmma::fragment<wmma::matrix_a, 16, 16, 8, wmma::precision::tf32, wmma::row_major> af[4];
            wmma::fragment<wmma::matrix_b, 16, 16, 8, wmma::precision::tf32, wmma::row_major> bf[WN];
#pragma unroll
            for (int i = 0; i < 4; i++) {
                wmma::load_matrix_sync(af[i], &As[(wm * 64 + i * 16) * LDA + ks], LDA);
#pragma unroll
                for (int t = 0; t < af[i].num_elements; t++)
                    af[i].x[t] = wmma::__float_to_tf32(af[i].x[t]);
            }
#pragma unroll
            for (int j = 0; j < WN; j++) {
                wmma::load_matrix_sync(bf[j], &Bs[ks * LDB + wn * WNT + j * 16], LDB);
#pragma unroll
                for (int t = 0; t < bf[j].num_elements; t++)
                    bf[j].x[t] = wmma::__float_to_tf32(bf[j].x[t]);
            }
#pragma unroll
            for (int i = 0; i < 4; i++)
#pragma unroll
                for (int j = 0; j < WN; j++)
                    wmma::mma_sync(acc[i][j], af[i], bf[j], acc[i][j]);
        }
        buf ^= 1;
        __syncthreads();
    }

    // ---- epilogue in two 64-row halves through smem ----
    float* CS = sbuf;
#pragma unroll
    for (int half = 0; half < 2; half++) {
        if (wm == half) {
#pragma unroll
            for (int i = 0; i < 4; i++)
#pragma unroll
                for (int j = 0; j < WN; j++)
                    wmma::store_matrix_sync(&CS[(i * 16) * LDB + wn * WNT + j * 16],
                                            acc[i][j], LDB, wmma::mem_row_major);
        }
        __syncthreads();
        constexpr int OS = 64 * GBN_T / 4;   // float4 slots in half
#pragma unroll
        for (int s = 0; s < OS; s += 256) {
            int sl = s + tid;
            int r = sl / (GBN_T / 4), c4 = sl % (GBN_T / 4);
            int gr = bm + half * 64 + r, gc = bn + c4 * 4;
            if (gr < M && gc < N) {
                float4 v = *reinterpret_cast<float4*>(&CS[r * LDB + c4 * 4]);
                *reinterpret_cast<float4*>(C + (size_t)gr * N + gc) = v;
            }
        }
        __syncthreads();
    }
}

// ---------------- attention scores: el[n,h]=<proj[n,h,:],al[h,:]> ----------------
template <int DH>
__global__ void scores_kernel(const float* __restrict__ proj,
                              const float* __restrict__ al, const float* __restrict__ ar,
                              float* __restrict__ el, float* __restrict__ er) {
    const int n = blockIdx.x;
    const int h = threadIdx.x >> 5;     // 4 warps = 4 heads
    const int lane = threadIdx.x & 31;
    const float* p = proj + (size_t)n * (4 * DH) + h * DH;
    float sl = 0.f, sr = 0.f;
    for (int c = lane; c < DH; c += 32) {
        float pv = p[c];
        sl = fmaf(pv, al[h * DH + c], sl);
        sr = fmaf(pv, ar[h * DH + c], sr);
    }
#pragma unroll
    for (int o = 16; o; o >>= 1) {
        sl += __shfl_down_sync(0xffffffffu, sl, o);
        sr += __shfl_down_sync(0xffffffffu, sr, o);
    }
    if (lane == 0) {
        el[n * 4 + h] = sl;
        er[n * 4 + h] = sr;
    }
}

// ---------------- CSR build ----------------
__global__ void zero_deg_kernel() {
    int i = blockIdx.x * blockDim.x + threadIdx.x;
    if (i < NN) g_deg[i] = 0;
}

__global__ void count_deg_kernel(const int* __restrict__ dst) {
    int e = blockIdx.x * blockDim.x + threadIdx.x;
    if (e < NE) atomicAdd(&g_deg[dst[e]], 1);
}

__global__ void scan_kernel() {
    __shared__ int sh[1024];
    const int t = threadIdx.x;
    const int CHUNK = (NN + 1023) / 1024;   // 49
    int beg = t * CHUNK;
    int end = min(beg + CHUNK, NN);
    int s = 0;
    for (int i = beg; i < end; i++) s += g_deg[i];
    sh[t] = s;
    __syncthreads();
    for (int off = 1; off < 1024; off <<= 1) {
        int v = (t >= off) ? sh[t - off] : 0;
        __syncthreads();
        sh[t] += v;
        __syncthreads();
    }
    int run = t ? sh[t - 1] : 0;
    for (int i = beg; i < end; i++) {
        g_rowptr[i] = run;
        g_cursor[i] = run;
        run += g_deg[i];
    }
    if (t == 0) g_rowptr[NN] = sh[1023];
}

__global__ void scatter_kernel(const int* __restrict__ src, const int* __restrict__ dst) {
    int e = blockIdx.x * blockDim.x + threadIdx.x;
    if (e < NE) {
        int p = atomicAdd(&g_cursor[dst[e]], 1);
        g_srcs[p] = src[e];
    }
}

// ---------------- per-dst softmax-weighted aggregation ----------------
template <int DH, bool ACT>
__global__ void aggregate_kernel(const float* __restrict__ proj,
                                 const float* __restrict__ el, const float* __restrict__ er,
                                 const float* __restrict__ bias, float* __restrict__ out) {
    const int CH = 4 * DH;
    const int d = blockIdx.x;
    const int t = threadIdx.x;
    const int beg = g_rowptr[d];
    const int end = g_rowptr[d + 1];

    const float4 erd = reinterpret_cast<const float4*>(er)[d];

    // phase 1: per-head running max
    float m0 = -1e30f, m1 = -1e30f, m2 = -1e30f, m3 = -1e30f;
    for (int e = beg; e < end; e++) {
        int sn = g_srcs[e];
        float4 l = reinterpret_cast<const float4*>(el)[sn];
        m0 = fmaxf(m0, lrelu(l.x + erd.x));
        m1 = fmaxf(m1, lrelu(l.y + erd.y));
        m2 = fmaxf(m2, lrelu(l.z + erd.z));
        m3 = fmaxf(m3, lrelu(l.w + erd.w));
    }

    int hd[4];
#pragma unroll
    for (int i = 0; i < 4; i++) {
        int c = t + 128 * i;
        hd[i] = (c < CH) ? (c / DH) : 0;
    }

    // phase 2: accumulate exp-weighted messages
    float acc[4] = {0.f, 0.f, 0.f, 0.f};
    float s0 = 0.f, s1 = 0.f, s2 = 0.f, s3 = 0.f;
    for (int e = beg; e < end; e++) {
        int sn = g_srcs[e];
        float4 l = reinterpret_cast<const float4*>(el)[sn];
        float ex[4];
        ex[0] = __expf(lrelu(l.x + erd.x) - m0); s0 += ex[0];
        ex[1] = __expf(lrelu(l.y + erd.y) - m1); s1 += ex[1];
        ex[2] = __expf(lrelu(l.z + erd.z) - m2); s2 += ex[2];
        ex[3] = __expf(lrelu(l.w + erd.w) - m3); s3 += ex[3];
        const float* pr = proj + (size_t)sn * CH;
#pragma unroll
        for (int i = 0; i < 4; i++) {
            int c = t + 128 * i;
            if (c < CH) acc[i] = fmaf(ex[hd[i]], pr[c], acc[i]);
        }
    }

    float sums[4] = {s0 + 1e-9f, s1 + 1e-9f, s2 + 1e-9f, s3 + 1e-9f};
#pragma unroll
    for (int i = 0; i < 4; i++) {
        int c = t + 128 * i;
        if (c < CH) {
            float v = acc[i] / sums[hd[i]] + bias[c];
            if (ACT) v = lrelu(v);
            out[(size_t)d * CH + c] = v;
        }
    }
}

// ---------------- launch ----------------
extern "C" void kernel_launch(void* const* d_in, const int* in_sizes, int n_in,
                              void* d_out, int out_size) {
    const float* x   = (const float*)d_in[0];
    const float* W1  = (const float*)d_in[1];
    const float* al1 = (const float*)d_in[2];
    const float* ar1 = (const float*)d_in[3];
    const float* b1  = (const float*)d_in[4];
    const float* W2  = (const float*)d_in[5];
    const float* al2 = (const float*)d_in[6];
    const float* ar2 = (const float*)d_in[7];
    const float* b2  = (const float*)d_in[8];
    const int*   src = (const int*)d_in[9];
    const int*   dst = (const int*)d_in[10];
    float* out = (float*)d_out;

    float *proj1, *h1, *proj2, *el1, *er1, *el2, *er2;
    cudaGetSymbolAddress((void**)&proj1, g_proj1);
    cudaGetSymbolAddress((void**)&h1, g_h1);
    cudaGetSymbolAddress((void**)&proj2, g_proj2);
    cudaGetSymbolAddress((void**)&el1, g_el1);
    cudaGetSymbolAddress((void**)&er1, g_er1);
    cudaGetSymbolAddress((void**)&el2, g_el2);
    cudaGetSymbolAddress((void**)&er2, g_er2);

    // CSR build (shared by both layers)
    zero_deg_kernel<<<(NN + 255) / 256, 256>>>();
    count_deg_kernel<<<(NE + 255) / 256, 256>>>(dst);
    scan_kernel<<<1, 1024>>>();
    scatter_kernel<<<(NE + 255) / 256, 256>>>(src, dst);

    // layer 1: GEMM N=400 -> 64-wide tiles (7 tiles, 11% pad)
    {
        dim3 grid((400 + 63) / 64, (NN + GBM - 1) / GBM);
        gemm_tf32_db<64><<<grid, 256>>>(x, W1, proj1, NN, 400, 300);
    }
    scores_kernel<100><<<NN, 128>>>(proj1, al1, ar1, el1, er1);
    aggregate_kernel<100, true><<<NN, 128>>>(proj1, el1, er1, b1, h1);

    // layer 2: GEMM N=512 -> 128-wide tiles (exact)
    {
        dim3 grid(512 / 128, (NN + GBM - 1) / GBM);
        gemm_tf32_db<128><<<grid, 256>>>(h1, W2, proj2, NN, 512, 400);
    }
    scores_kernel<128><<<NN, 128>>>(proj2, al2, ar2, el2, er2);
    aggregate_kernel<128, false><<<NN, 128>>>(proj2, el2, er2, b2, out);
}

// round 4
// speedup vs baseline: 2.1274x; 1.3677x over previous
#include <cuda_runtime.h>
#include <mma.h>
#include <math.h>

using namespace nvcuda;

#define NN 50000
#define NE 800000
#define NHEADS 4
#define SLOPE 0.2f

// ---------------- scratch (static device globals; no allocation) ----------------
__device__ float g_proj1[NN * 400];   // 80 MB
__device__ float g_h1[NN * 400];      // 80 MB
__device__ float g_proj2[NN * 512];   // 102.4 MB
__device__ float g_el1[NN * NHEADS];
__device__ float g_er1[NN * NHEADS];
__device__ float g_el2[NN * NHEADS];
__device__ float g_er2[NN * NHEADS];
__device__ float g_alpha[NE * 4];     // per-edge, per-head normalized weights (12.8MB)
__device__ int   g_deg[NN];
__device__ int   g_rowptr[NN + 1];
__device__ int   g_cursor[NN];
__device__ int   g_srcs[NE];          // src ids sorted by dst (CSR payload)

__device__ __forceinline__ float lrelu(float x) { return x > 0.f ? x : SLOPE * x; }

// ---------------- cp.async helpers ----------------
__device__ __forceinline__ void cp_async16(void* smem, const void* g) {
    unsigned saddr = (unsigned)__cvta_generic_to_shared(smem);
    asm volatile("cp.async.cg.shared.global [%0], [%1], 16;\n" :: "r"(saddr), "l"(g));
}
__device__ __forceinline__ void cp_commit() { asm volatile("cp.async.commit_group;\n" ::: "memory"); }
__device__ __forceinline__ void cp_wait0()  { asm volatile("cp.async.wait_group 0;\n" ::: "memory"); }

// ---------------- TF32 WMMA GEMM, double-buffered cp.async pipeline ----------------
#define GBM 128
#define GBK 16
#define LDA 20

template <int GBN_T>
__global__ void __launch_bounds__(256, 2)
gemm_tf32_db(const float* __restrict__ A, const float* __restrict__ B,
             float* __restrict__ C, int M, int N, int K) {
    constexpr int LDB  = GBN_T + 4;
    constexpr int WN   = GBN_T / 64;
    constexpr int WNT  = WN * 16;
    constexpr int ABUF = GBM * LDA;
    constexpr int BBUF = GBK * LDB;
    constexpr int TILEBUF = ABUF + BBUF;
    constexpr int STAGE   = 64 * LDB;
    constexpr int SMEMF   = (2 * TILEBUF > STAGE) ? 2 * TILEBUF : STAGE;

    __shared__ float sbuf[SMEMF];

    const int tid  = threadIdx.x;
    const int warp = tid >> 5;
    const int wm   = warp & 1;
    const int wn   = warp >> 1;
    const int bm   = blockIdx.y * GBM;
    const int bn   = blockIdx.x * GBN_T;

    wmma::fragment<wmma::accumulator, 16, 16, 8, float> acc[4][WN];
#pragma unroll
    for (int i = 0; i < 4; i++)
#pragma unroll
        for (int j = 0; j < WN; j++) wmma::fill_fragment(acc[i][j], 0.f);

    auto load_tile = [&](int buf, int kt) {
        float* As = sbuf + buf * TILEBUF;
        float* Bs = As + ABUF;
#pragma unroll
        for (int it = 0; it < 2; it++) {
            int s = tid + 256 * it;
            int r = s >> 2, c4 = s & 3;
            int gr = bm + r, gc = kt + c4 * 4;
            float* dstp = &As[r * LDA + c4 * 4];
            if (gr < M && gc < K) cp_async16(dstp, A + (size_t)gr * K + gc);
            else *reinterpret_cast<float4*>(dstp) = make_float4(0.f, 0.f, 0.f, 0.f);
        }
        constexpr int BS = GBK * GBN_T / 4;
#pragma unroll
        for (int s = 0; s < BS; s += 256) {
            int sl = s + tid;
            int r = sl / (GBN_T / 4), c4 = sl % (GBN_T / 4);
            int gr = kt + r, gc = bn + c4 * 4;
            float* dstp = &Bs[r * LDB + c4 * 4];
            if (gr < K && gc < N) cp_async16(dstp, B + (size_t)gr * N + gc);
            else *reinterpret_cast<float4*>(dstp) = make_float4(0.f, 0.f, 0.f, 0.f);
        }
        cp_commit();
    };

    load_tile(0, 0);

    int buf = 0;
    for (int kt = 0; kt < K; kt += GBK) {
        cp_wait0();
        __syncthreads();
        if (kt + GBK < K) load_tile(buf ^ 1, kt + GBK);

        const float* As = sbuf + buf * TILEBUF;
        const float* Bs = As + ABUF;
#pragma unroll
        for (int ks = 0; ks < GBK; ks += 8) {
            wmma::fragment<wmma::matrix_a, 16, 16, 8, wmma::precision::tf32, wmma::row_major> af[4];
            wmma::fragment<wmma::matrix_b, 16, 16, 8, wmma::precision::tf32, wmma::row_major> bf[WN];
#pragma unroll
            for (int i = 0; i < 4; i++) {
                wmma::load_matrix_sync(af[i], &As[(wm * 64 + i * 16) * LDA + ks], LDA);
#pragma unroll
                for (int t = 0; t < af[i].num_elements; t++)
                    af[i].x[t] = wmma::__float_to_tf32(af[i].x[t]);
            }
#pragma unroll
            for (int j = 0; j < WN; j++) {
                wmma::load_matrix_sync(bf[j], &Bs[ks * LDB + wn * WNT + j * 16], LDB);
#pragma unroll
                for (int t = 0; t < bf[j].num_elements; t++)
                    bf[j].x[t] = wmma::__float_to_tf32(bf[j].x[t]);
            }
#pragma unroll
            for (int i = 0; i < 4; i++)
#pragma unroll
                for (int j = 0; j < WN; j++)
                    wmma::mma_sync(acc[i][j], af[i], bf[j], acc[i][j]);
        }
        buf ^= 1;
        __syncthreads();
    }

    float* CS = sbuf;
#pragma unroll
    for (int half = 0; half < 2; half++) {
        if (wm == half) {
#pragma unroll
            for (int i = 0; i < 4; i++)
#pragma unroll
                for (int j = 0; j < WN; j++)
                    wmma::store_matrix_sync(&CS[(i * 16) * LDB + wn * WNT + j * 16],
                                            acc[i][j], LDB, wmma::mem_row_major);
        }
        __syncthreads();
        constexpr int OS = 64 * GBN_T / 4;
#pragma unroll
        for (int s = 0; s < OS; s += 256) {
            int sl = s + tid;
            int r = sl / (GBN_T / 4), c4 = sl % (GBN_T / 4);
            int gr = bm + half * 64 + r, gc = bn + c4 * 4;
            if (gr < M && gc < N) {
                float4 v = *reinterpret_cast<float4*>(&CS[r * LDB + c4 * 4]);
                *reinterpret_cast<float4*>(C + (size_t)gr * N + gc) = v;
            }
        }
        __syncthreads();
    }
}

// ---------------- attention scores: el[n,h]=<proj[n,h,:],al[h,:]> ----------------
template <int DH>
__global__ void scores_kernel(const float* __restrict__ proj,
                              const float* __restrict__ al, const float* __restrict__ ar,
                              float* __restrict__ el, float* __restrict__ er) {
    const int n = blockIdx.x;
    const int h = threadIdx.x >> 5;
    const int lane = threadIdx.x & 31;
    const float* p = proj + (size_t)n * (4 * DH) + h * DH;
    float sl = 0.f, sr = 0.f;
    for (int c = lane; c < DH; c += 32) {
        float pv = p[c];
        sl = fmaf(pv, al[h * DH + c], sl);
        sr = fmaf(pv, ar[h * DH + c], sr);
    }
#pragma unroll
    for (int o = 16; o; o >>= 1) {
        sl += __shfl_down_sync(0xffffffffu, sl, o);
        sr += __shfl_down_sync(0xffffffffu, sr, o);
    }
    if (lane == 0) {
        el[n * 4 + h] = sl;
        er[n * 4 + h] = sr;
    }
}

// ---------------- CSR build ----------------
__global__ void zero_deg_kernel() {
    int i = blockIdx.x * blockDim.x + threadIdx.x;
    if (i < NN) g_deg[i] = 0;
}

__global__ void count_deg_kernel(const int* __restrict__ dst) {
    int e = blockIdx.x * blockDim.x + threadIdx.x;
    if (e < NE) atomicAdd(&g_deg[dst[e]], 1);
}

__global__ void scan_kernel() {
    __shared__ int sh[1024];
    const int t = threadIdx.x;
    const int CHUNK = (NN + 1023) / 1024;
    int beg = t * CHUNK;
    int end = min(beg + CHUNK, NN);
    int s = 0;
    for (int i = beg; i < end; i++) s += g_deg[i];
    sh[t] = s;
    __syncthreads();
    for (int off = 1; off < 1024; off <<= 1) {
        int v = (t >= off) ? sh[t - off] : 0;
        __syncthreads();
        sh[t] += v;
        __syncthreads();
    }
    int run = t ? sh[t - 1] : 0;
    for (int i = beg; i < end; i++) {
        g_rowptr[i] = run;
        g_cursor[i] = run;
        run += g_deg[i];
    }
    if (t == 0) g_rowptr[NN] = sh[1023];
}

__global__ void scatter_kernel(const int* __restrict__ src, const int* __restrict__ dst) {
    int e = blockIdx.x * blockDim.x + threadIdx.x;
    if (e < NE) {
        int p = atomicAdd(&g_cursor[dst[e]], 1);
        g_srcs[p] = src[e];
    }
}

// ---------------- per-dst softmax weights: one warp per dst node ----------------
// lanes parallel over edges of the dst segment; writes normalized alpha[e][4].
__global__ void alpha_kernel(const float* __restrict__ el, const float* __restrict__ er,
                             float* __restrict__ alpha) {
    const int d = blockIdx.x * 8 + (threadIdx.x >> 5);
    if (d >= NN) return;
    const int lane = threadIdx.x & 31;
    const int beg = g_rowptr[d];
    const int end = g_rowptr[d + 1];

    const float4 erd = reinterpret_cast<const float4*>(er)[d];

    // pass 1: scores -> alpha (raw), running per-lane max
    float4 m = make_float4(-1e30f, -1e30f, -1e30f, -1e30f);
    for (int e = beg + lane; e < end; e += 32) {
        int sn = g_srcs[e];
        float4 l = reinterpret_cast<const float4*>(el)[sn];
        float4 v;
        v.x = lrelu(l.x + erd.x);
        v.y = lrelu(l.y + erd.y);
        v.z = lrelu(l.z + erd.z);
        v.w = lrelu(l.w + erd.w);
        reinterpret_cast<float4*>(alpha)[e] = v;
        m.x = fmaxf(m.x, v.x); m.y = fmaxf(m.y, v.y);
        m.z = fmaxf(m.z, v.z); m.w = fmaxf(m.w, v.w);
    }
#pragma unroll
    for (int o = 16; o; o >>= 1) {
        m.x = fmaxf(m.x, __shfl_xor_sync(0xffffffffu, m.x, o));
        m.y = fmaxf(m.y, __shfl_xor_sync(0xffffffffu, m.y, o));
        m.z = fmaxf(m.z, __shfl_xor_sync(0xffffffffu, m.z, o));
        m.w = fmaxf(m.w, __shfl_xor_sync(0xffffffffu, m.w, o));
    }

    // pass 2: exp, running sum
    float4 s = make_float4(0.f, 0.f, 0.f, 0.f);
    for (int e = beg + lane; e < end; e += 32) {
        float4 v = reinterpret_cast<float4*>(alpha)[e];
        v.x = __expf(v.x - m.x); v.y = __expf(v.y - m.y);
        v.z = __expf(v.z - m.z); v.w = __expf(v.w - m.w);
        reinterpret_cast<float4*>(alpha)[e] = v;
        s.x += v.x; s.y += v.y; s.z += v.z; s.w += v.w;
    }
#pragma unroll
    for (int o = 16; o; o >>= 1) {
        s.x += __shfl_xor_sync(0xffffffffu, s.x, o);
        s.y += __shfl_xor_sync(0xffffffffu, s.y, o);
        s.z += __shfl_xor_sync(0xffffffffu, s.z, o);
        s.w += __shfl_xor_sync(0xffffffffu, s.w, o);
    }
    float4 inv;
    inv.x = 1.f / (s.x + 1e-9f); inv.y = 1.f / (s.y + 1e-9f);
    inv.z = 1.f / (s.z + 1e-9f); inv.w = 1.f / (s.w + 1e-9f);

    // pass 3: normalize
    for (int e = beg + lane; e < end; e += 32) {
        float4 v = reinterpret_cast<float4*>(alpha)[e];
        v.x *= inv.x; v.y *= inv.y; v.z *= inv.z; v.w *= inv.w;
        reinterpret_cast<float4*>(alpha)[e] = v;
    }
}

// ---------------- lean aggregation: acc4 += alpha[e][head] * proj4[src] ----------------
template <int DH, bool ACT>
__global__ void aggregate_kernel(const float* __restrict__ proj,
                                 const float* __restrict__ alpha,
                                 const float* __restrict__ bias, float* __restrict__ out) {
    constexpr int C4 = DH;   // CH/4 = 4*DH/4
    const int d = blockIdx.x;
    const int t = threadIdx.x;
    const int beg = g_rowptr[d];
    const int end = g_rowptr[d + 1];
    if (t >= C4) return;

    const int head = t / (DH / 4);   // float4-aligned head boundaries (4 | DH)

    float4 acc = make_float4(0.f, 0.f, 0.f, 0.f);
#pragma unroll 2
    for (int e = beg; e < end; e++) {
        int sn = g_srcs[e];
        float4 a = reinterpret_cast<const float4*>(alpha)[e];   // broadcast
        float w = (head == 0) ? a.x : (head == 1) ? a.y : (head == 2) ? a.z : a.w;
        float4 p = reinterpret_cast<const float4*>(proj)[(size_t)sn * C4 + t];
        acc.x = fmaf(w, p.x, acc.x);
        acc.y = fmaf(w, p.y, acc.y);
        acc.z = fmaf(w, p.z, acc.z);
        acc.w = fmaf(w, p.w, acc.w);
    }
    float4 b = reinterpret_cast<const float4*>(bias)[t];
    acc.x += b.x; acc.y += b.y; acc.z += b.z; acc.w += b.w;
    if (ACT) {
        acc.x = lrelu(acc.x); acc.y = lrelu(acc.y);
        acc.z = lrelu(acc.z); acc.w = lrelu(acc.w);
    }
    reinterpret_cast<float4*>(out)[(size_t)d * C4 + t] = acc;
}

// ---------------- launch ----------------
extern "C" void kernel_launch(void* const* d_in, const int* in_sizes, int n_in,
                              void* d_out, int out_size) {
    const float* x   = (const float*)d_in[0];
    const float* W1  = (const float*)d_in[1];
    const float* al1 = (const float*)d_in[2];
    const float* ar1 = (const float*)d_in[3];
    const float* b1  = (const float*)d_in[4];
    const float* W2  = (const float*)d_in[5];
    const float* al2 = (const float*)d_in[6];
    const float* ar2 = (const float*)d_in[7];
    const float* b2  = (const float*)d_in[8];
    const int*   src = (const int*)d_in[9];
    const int*   dst = (const int*)d_in[10];
    float* out = (float*)d_out;

    float *proj1, *h1, *proj2, *el1, *er1, *el2, *er2, *alpha;
    cudaGetSymbolAddress((void**)&proj1, g_proj1);
    cudaGetSymbolAddress((void**)&h1, g_h1);
    cudaGetSymbolAddress((void**)&proj2, g_proj2);
    cudaGetSymbolAddress((void**)&el1, g_el1);
    cudaGetSymbolAddress((void**)&er1, g_er1);
    cudaGetSymbolAddress((void**)&el2, g_el2);
    cudaGetSymbolAddress((void**)&er2, g_er2);
    cudaGetSymbolAddress((void**)&alpha, g_alpha);

    // CSR build (shared by both layers)
    zero_deg_kernel<<<(NN + 255) / 256, 256>>>();
    count_deg_kernel<<<(NE + 255) / 256, 256>>>(dst);
    scan_kernel<<<1, 1024>>>();
    scatter_kernel<<<(NE + 255) / 256, 256>>>(src, dst);

    const int ABLK = (NN + 7) / 8;

    // layer 1
    {
        dim3 grid((400 + 63) / 64, (NN + GBM - 1) / GBM);
        gemm_tf32_db<64><<<grid, 256>>>(x, W1, proj1, NN, 400, 300);
    }
    scores_kernel<100><<<NN, 128>>>(proj1, al1, ar1, el1, er1);
    alpha_kernel<<<ABLK, 256>>>(el1, er1, alpha);
    aggregate_kernel<100, true><<<NN, 128>>>(proj1, alpha, b1, h1);

    // layer 2
    {
        dim3 grid(512 / 128, (NN + GBM - 1) / GBM);
        gemm_tf32_db<128><<<grid, 256>>>(h1, W2, proj2, NN, 512, 400);
    }
    scores_kernel<128><<<NN, 128>>>(proj2, al2, ar2, el2, er2);
    alpha_kernel<<<ABLK, 256>>>(el2, er2, alpha);
    aggregate_kernel<128, false><<<NN, 128>>>(proj2, alpha, b2, out);
}

// round 6
// speedup vs baseline: 2.2248x; 1.0458x over previous
#include <cuda_runtime.h>
#include <cuda_fp16.h>
#include <mma.h>
#include <math.h>

using namespace nvcuda;

#define NN 50000
#define NE 800000
#define NHEADS 4
#define SLOPE 0.2f

// ---------------- scratch (static device globals; no allocation) ----------------
__device__ float g_proj1[NN * 400];      // 80 MB (fp32, for scores)
__device__ float g_h1[NN * 400];         // 80 MB
__device__ float g_proj2[NN * 512];      // 102.4 MB
__device__ __half g_projh1[NN * 400];    // 40 MB (fp16, for aggregation gather)
__device__ __half g_projh2[NN * 512];    // 51.2 MB
__device__ float g_el1[NN * NHEADS];
__device__ float g_er1[NN * NHEADS];
__device__ float g_el2[NN * NHEADS];
__device__ float g_er2[NN * NHEADS];
__device__ float g_alpha[NE * 4];        // per-edge normalized weights (12.8MB)
__device__ int   g_deg[NN];
__device__ int   g_rowptr[NN + 1];
__device__ int   g_cursor[NN];
__device__ int   g_srcs[NE];

__device__ __forceinline__ float lrelu(float x) { return x > 0.f ? x : SLOPE * x; }

// ---------------- cp.async helpers ----------------
__device__ __forceinline__ void cp_async16(void* smem, const void* g) {
    unsigned saddr = (unsigned)__cvta_generic_to_shared(smem);
    asm volatile("cp.async.cg.shared.global [%0], [%1], 16;\n" :: "r"(saddr), "l"(g));
}
__device__ __forceinline__ void cp_commit() { asm volatile("cp.async.commit_group;\n" ::: "memory"); }
__device__ __forceinline__ void cp_wait0()  { asm volatile("cp.async.wait_group 0;\n" ::: "memory"); }
__device__ __forceinline__ void cp_wait1()  { asm volatile("cp.async.wait_group 1;\n" ::: "memory"); }

// ---------------- TF32 WMMA GEMM, 3-stage cp.async pipeline ----------------
#define GBM 128
#define GBK 16
#define LDA 20

template <int GBN_T>
__global__ void __launch_bounds__(256, 2)
gemm_tf32_db(const float* __restrict__ A, const float* __restrict__ B,
             float* __restrict__ C, __half* __restrict__ Ch,
             int M, int N, int K) {
    constexpr int LDB  = GBN_T + 4;
    constexpr int WN   = GBN_T / 64;
    constexpr int WNT  = WN * 16;
    constexpr int ABUF = GBM * LDA;
    constexpr int BBUF = GBK * LDB;
    constexpr int TILEBUF = ABUF + BBUF;
    constexpr int STAGE   = 64 * LDB;
    constexpr int SMEMF   = (3 * TILEBUF > STAGE) ? 3 * TILEBUF : STAGE;

    __shared__ float sbuf[SMEMF];

    const int tid  = threadIdx.x;
    const int warp = tid >> 5;
    const int wm   = warp & 1;
    const int wn   = warp >> 1;
    const int bm   = blockIdx.y * GBM;
    const int bn   = blockIdx.x * GBN_T;

    wmma::fragment<wmma::accumulator, 16, 16, 8, float> acc[4][WN];
#pragma unroll
    for (int i = 0; i < 4; i++)
#pragma unroll
        for (int j = 0; j < WN; j++) wmma::fill_fragment(acc[i][j], 0.f);

    auto load_tile = [&](int buf, int kt) {
        float* As = sbuf + buf * TILEBUF;
        float* Bs = As + ABUF;
#pragma unroll
        for (int it = 0; it < 2; it++) {
            int s = tid + 256 * it;
            int r = s >> 2, c4 = s & 3;
            int gr = bm + r, gc = kt + c4 * 4;
            float* dstp = &As[r * LDA + c4 * 4];
            if (gr < M && gc < K) cp_async16(dstp, A + (size_t)gr * K + gc);
            else *reinterpret_cast<float4*>(dstp) = make_float4(0.f, 0.f, 0.f, 0.f);
        }
        constexpr int BS = GBK * GBN_T / 4;
#pragma unroll
        for (int s = 0; s < BS; s += 256) {
            int sl = s + tid;
            int r = sl / (GBN_T / 4), c4 = sl % (GBN_T / 4);
            int gr = kt + r, gc = bn + c4 * 4;
            float* dstp = &Bs[r * LDB + c4 * 4];
            if (gr < K && gc < N) cp_async16(dstp, B + (size_t)gr * N + gc);
            else *reinterpret_cast<float4*>(dstp) = make_float4(0.f, 0.f, 0.f, 0.f);
        }
        cp_commit();
    };

    // prologue: 2 tiles in flight
    load_tile(0, 0);
    if (GBK < K) load_tile(1, GBK);

    int buf = 0;
    for (int kt = 0; kt < K; kt += GBK) {
        if (kt + GBK < K) cp_wait1(); else cp_wait0();
        __syncthreads();
        if (kt + 2 * GBK < K) load_tile((buf + 2) % 3, kt + 2 * GBK);

        const float* As = sbuf + buf * TILEBUF;
        const float* Bs = As + ABUF;
#pragma unroll
        for (int ks = 0; ks < GBK; ks += 8) {
            wmma::fragment<wmma::matrix_a, 16, 16, 8, wmma::precision::tf32, wmma::row_major> af[4];
            wmma::fragment<wmma::matrix_b, 16, 16, 8, wmma::precision::tf32, wmma::row_major> bf[WN];
#pragma unroll
            for (int i = 0; i < 4; i++) {
                wmma::load_matrix_sync(af[i], &As[(wm * 64 + i * 16) * LDA + ks], LDA);
#pragma unroll
                for (int t = 0; t < af[i].num_elements; t++)
                    af[i].x[t] = wmma::__float_to_tf32(af[i].x[t]);
            }
#pragma unroll
            for (int j = 0; j < WN; j++) {
                wmma::load_matrix_sync(bf[j], &Bs[ks * LDB + wn * WNT + j * 16], LDB);
#pragma unroll
                for (int t = 0; t < bf[j].num_elements; t++)
                    bf[j].x[t] = wmma::__float_to_tf32(bf[j].x[t]);
            }
#pragma unroll
            for (int i = 0; i < 4; i++)
#pragma unroll
                for (int j = 0; j < WN; j++)
                    wmma::mma_sync(acc[i][j], af[i], bf[j], acc[i][j]);
        }
        buf = (buf + 1) % 3;
        __syncthreads();
    }

    // ---- epilogue in two 64-row halves through smem; dual-write fp32 + fp16 ----
    float* CS = sbuf;
#pragma unroll
    for (int half = 0; half < 2; half++) {
        if (wm == half) {
#pragma unroll
            for (int i = 0; i < 4; i++)
#pragma unroll
                for (int j = 0; j < WN; j++)
                    wmma::store_matrix_sync(&CS[(i * 16) * LDB + wn * WNT + j * 16],
                                            acc[i][j], LDB, wmma::mem_row_major);
        }
        __syncthreads();
        constexpr int OS = 64 * GBN_T / 4;
#pragma unroll
        for (int s = 0; s < OS; s += 256) {
            int sl = s + tid;
            int r = sl / (GBN_T / 4), c4 = sl % (GBN_T / 4);
            int gr = bm + half * 64 + r, gc = bn + c4 * 4;
            if (gr < M && gc < N) {
                float4 v = *reinterpret_cast<float4*>(&CS[r * LDB + c4 * 4]);
                *reinterpret_cast<float4*>(C + (size_t)gr * N + gc) = v;
                __half2 h0 = __floats2half2_rn(v.x, v.y);
                __half2 h1 = __floats2half2_rn(v.z, v.w);
                *reinterpret_cast<__half2*>(Ch + (size_t)gr * N + gc)     = h0;
                *reinterpret_cast<__half2*>(Ch + (size_t)gr * N + gc + 2) = h1;
            }
        }
        __syncthreads();
    }
}

// ---------------- attention scores ----------------
template <int DH>
__global__ void scores_kernel(const float* __restrict__ proj,
                              const float* __restrict__ al, const float* __restrict__ ar,
                              float* __restrict__ el, float* __restrict__ er) {
    const int n = blockIdx.x;
    const int h = threadIdx.x >> 5;
    const int lane = threadIdx.x & 31;
    const float* p = proj + (size_t)n * (4 * DH) + h * DH;
    float sl = 0.f, sr = 0.f;
    for (int c = lane; c < DH; c += 32) {
        float pv = p[c];
        sl = fmaf(pv, al[h * DH + c], sl);
        sr = fmaf(pv, ar[h * DH + c], sr);
    }
#pragma unroll
    for (int o = 16; o; o >>= 1) {
        sl += __shfl_down_sync(0xffffffffu, sl, o);
        sr += __shfl_down_sync(0xffffffffu, sr, o);
    }
    if (lane == 0) {
        el[n * 4 + h] = sl;
        er[n * 4 + h] = sr;
    }
}

// ---------------- CSR build ----------------
__global__ void count_deg_kernel(const int* __restrict__ dst) {
    int e = blockIdx.x * blockDim.x + threadIdx.x;
    if (e < NE) atomicAdd(&g_deg[dst[e]], 1);
}

__global__ void scan_kernel() {
    __shared__ int sh[1024];
    const int t = threadIdx.x;
    const int CHUNK = (NN + 1023) / 1024;
    int beg = t * CHUNK;
    int end = min(beg + CHUNK, NN);
    int s = 0;
    for (int i = beg; i < end; i++) s += g_deg[i];
    sh[t] = s;
    __syncthreads();
    for (int off = 1; off < 1024; off <<= 1) {
        int v = (t >= off) ? sh[t - off] : 0;
        __syncthreads();
        sh[t] += v;
        __syncthreads();
    }
    int run = t ? sh[t - 1] : 0;
    for (int i = beg; i < end; i++) {
        g_rowptr[i] = run;
        g_cursor[i] = run;
        run += g_deg[i];
    }
    if (t == 0) g_rowptr[NN] = sh[1023];
}

__global__ void scatter_kernel(const int* __restrict__ src, const int* __restrict__ dst) {
    int e = blockIdx.x * blockDim.x + threadIdx.x;
    if (e < NE) {
        int p = atomicAdd(&g_cursor[dst[e]], 1);
        g_srcs[p] = src[e];
    }
}

// ---------------- per-dst softmax weights: one warp per dst node ----------------
__global__ void alpha_kernel(const float* __restrict__ el, const float* __restrict__ er,
                             float* __restrict__ alpha) {
    const int d = blockIdx.x * 8 + (threadIdx.x >> 5);
    if (d >= NN) return;
    const int lane = threadIdx.x & 31;
    const int beg = g_rowptr[d];
    const int end = g_rowptr[d + 1];

    const float4 erd = reinterpret_cast<const float4*>(er)[d];

    float4 m = make_float4(-1e30f, -1e30f, -1e30f, -1e30f);
    for (int e = beg + lane; e < end; e += 32) {
        int sn = g_srcs[e];
        float4 l = reinterpret_cast<const float4*>(el)[sn];
        float4 v;
        v.x = lrelu(l.x + erd.x);
        v.y = lrelu(l.y + erd.y);
        v.z = lrelu(l.z + erd.z);
        v.w = lrelu(l.w + erd.w);
        reinterpret_cast<float4*>(alpha)[e] = v;
        m.x = fmaxf(m.x, v.x); m.y = fmaxf(m.y, v.y);
        m.z = fmaxf(m.z, v.z); m.w = fmaxf(m.w, v.w);
    }
#pragma unroll
    for (int o = 16; o; o >>= 1) {
        m.x = fmaxf(m.x, __shfl_xor_sync(0xffffffffu, m.x, o));
        m.y = fmaxf(m.y, __shfl_xor_sync(0xffffffffu, m.y, o));
        m.z = fmaxf(m.z, __shfl_xor_sync(0xffffffffu, m.z, o));
        m.w = fmaxf(m.w, __shfl_xor_sync(0xffffffffu, m.w, o));
    }

    float4 s = make_float4(0.f, 0.f, 0.f, 0.f);
    for (int e = beg + lane; e < end; e += 32) {
        float4 v = reinterpret_cast<float4*>(alpha)[e];
        v.x = __expf(v.x - m.x); v.y = __expf(v.y - m.y);
        v.z = __expf(v.z - m.z); v.w = __expf(v.w - m.w);
        reinterpret_cast<float4*>(alpha)[e] = v;
        s.x += v.x; s.y += v.y; s.z += v.z; s.w += v.w;
    }
#pragma unroll
    for (int o = 16; o; o >>= 1) {
        s.x += __shfl_xor_sync(0xffffffffu, s.x, o);
        s.y += __shfl_xor_sync(0xffffffffu, s.y, o);
        s.z += __shfl_xor_sync(0xffffffffu, s.z, o);
        s.w += __shfl_xor_sync(0xffffffffu, s.w, o);
    }
    float4 inv;
    inv.x = 1.f / (s.x + 1e-9f); inv.y = 1.f / (s.y + 1e-9f);
    inv.z = 1.f / (s.z + 1e-9f); inv.w = 1.f / (s.w + 1e-9f);

    for (int e = beg + lane; e < end; e += 32) {
        float4 v = reinterpret_cast<float4*>(alpha)[e];
        v.x *= inv.x; v.y *= inv.y; v.z *= inv.z; v.w *= inv.w;
        reinterpret_cast<float4*>(alpha)[e] = v;
    }
}

// ---------------- aggregation over fp16 proj: acc4 += alpha[e][head] * projh4[src] ----------------
template <int DH, bool ACT>
__global__ void aggregate_kernel(const __half* __restrict__ projh,
                                 const float* __restrict__ alpha,
                                 const float* __restrict__ bias, float* __restrict__ out) {
    constexpr int C4 = DH;
    const int d = blockIdx.x;
    const int t = threadIdx.x;
    const int beg = g_rowptr[d];
    const int end = g_rowptr[d + 1];
    if (t >= C4) return;

    const int head = (4 * t) / DH;

    float4 acc = make_float4(0.f, 0.f, 0.f, 0.f);
#pragma unroll 2
    for (int e = beg; e < end; e++) {
        int sn = g_srcs[e];
        float4 a = reinterpret_cast<const float4*>(alpha)[e];   // broadcast
        float w = (head == 0) ? a.x : (head == 1) ? a.y : (head == 2) ? a.z : a.w;
        const __half2* ph =
            reinterpret_cast<const __half2*>(projh + (size_t)sn * (4 * DH)) + 2 * t;
        float2 p0 = __half22float2(ph[0]);
        float2 p1 = __half22float2(ph[1]);
        acc.x = fmaf(w, p0.x, acc.x);
        acc.y = fmaf(w, p0.y, acc.y);
        acc.z = fmaf(w, p1.x, acc.z);
        acc.w = fmaf(w, p1.y, acc.w);
    }
    float4 b = reinterpret_cast<const float4*>(bias)[t];
    acc.x += b.x; acc.y += b.y; acc.z += b.z; acc.w += b.w;
    if (ACT) {
        acc.x = lrelu(acc.x); acc.y = lrelu(acc.y);
        acc.z = lrelu(acc.z); acc.w = lrelu(acc.w);
    }
    reinterpret_cast<float4*>(out)[(size_t)d * C4 + t] = acc;
}

// ---------------- launch ----------------
extern "C" void kernel_launch(void* const* d_in, const int* in_sizes, int n_in,
                              void* d_out, int out_size) {
    const float* x   = (const float*)d_in[0];
    const float* W1  = (const float*)d_in[1];
    const float* al1 = (const float*)d_in[2];
    const float* ar1 = (const float*)d_in[3];
    const float* b1  = (const float*)d_in[4];
    const float* W2  = (const float*)d_in[5];
    const float* al2 = (const float*)d_in[6];
    const float* ar2 = (const float*)d_in[7];
    const float* b2  = (const float*)d_in[8];
    const int*   src = (const int*)d_in[9];
    const int*   dst = (const int*)d_in[10];
    float* out = (float*)d_out;

    float *proj1, *h1, *proj2, *el1, *er1, *el2, *er2, *alpha, *degp;
    __half *projh1, *projh2;
    cudaGetSymbolAddress((void**)&proj1, g_proj1);
    cudaGetSymbolAddress((void**)&h1, g_h1);
    cudaGetSymbolAddress((void**)&proj2, g_proj2);
    cudaGetSymbolAddress((void**)&projh1, g_projh1);
    cudaGetSymbolAddress((void**)&projh2, g_projh2);
    cudaGetSymbolAddress((void**)&el1, g_el1);
    cudaGetSymbolAddress((void**)&er1, g_er1);
    cudaGetSymbolAddress((void**)&el2, g_el2);
    cudaGetSymbolAddress((void**)&er2, g_er2);
    cudaGetSymbolAddress((void**)&alpha, g_alpha);
    cudaGetSymbolAddress((void**)&degp, g_deg);

    // CSR build
    cudaMemsetAsync(degp, 0, NN * sizeof(int));
    count_deg_kernel<<<(NE + 255) / 256, 256>>>(dst);
    scan_kernel<<<1, 1024>>>();
    scatter_kernel<<<(NE + 255) / 256, 256>>>(src, dst);

    const int ABLK = (NN + 7) / 8;

    // layer 1
    {
        dim3 grid((400 + 63) / 64, (NN + GBM - 1) / GBM);
        gemm_tf32_db<64><<<grid, 256>>>(x, W1, proj1, projh1, NN, 400, 300);
    }
    scores_kernel<100><<<NN, 128>>>(proj1, al1, ar1, el1, er1);
    alpha_kernel<<<ABLK, 256>>>(el1, er1, alpha);
    aggregate_kernel<100, true><<<NN, 128>>>(projh1, alpha, b1, h1);

    // layer 2
    {
        dim3 grid(512 / 128, (NN + GBM - 1) / GBM);
        gemm_tf32_db<128><<<grid, 256>>>(h1, W2, proj2, projh2, NN, 512, 400);
    }
    scores_kernel<128><<<NN, 128>>>(proj2, al2, ar2, el2, er2);
    alpha_kernel<<<ABLK, 256>>>(el2, er2, alpha);
    aggregate_kernel<128, false><<<NN, 128>>>(projh2, alpha, b2, out);
}

// round 8
// speedup vs baseline: 2.2698x; 1.0202x over previous
#include <cuda_runtime.h>
#include <cuda_fp16.h>
#include <mma.h>
#include <math.h>

using namespace nvcuda;

#define NN 50000
#define NE 800000
#define NHEADS 4
#define SLOPE 0.2f

// ---------------- scratch (static device globals; no allocation) ----------------
__device__ float g_proj1[NN * 400];      // 80 MB (fp32, for scores)
__device__ float g_h1[NN * 400];         // 80 MB (tf32-rounded at write)
__device__ float g_proj2[NN * 512];      // 102.4 MB
__device__ float g_xr[NN * 300];         // 60 MB (tf32-rounded input x)
__device__ float g_w1r[300 * 400];       // tf32-rounded W1
__device__ float g_w2r[400 * 512];       // tf32-rounded W2
__device__ __half g_projh1[NN * 400];    // 40 MB (fp16, for aggregation gather)
__device__ __half g_projh2[NN * 512];    // 51.2 MB
__device__ float g_el1[NN * NHEADS];
__device__ float g_er1[NN * NHEADS];
__device__ float g_el2[NN * NHEADS];
__device__ float g_er2[NN * NHEADS];
__device__ float g_alpha[NE * 4];        // per-edge UNNORMALIZED exp weights
__device__ float g_inv[NN * 4];          // per-dst, per-head 1/(sum+eps)
__device__ int   g_deg[NN];
__device__ int   g_rowptr[NN + 1];
__device__ int   g_cursor[NN];
__device__ int   g_srcs[NE];

__device__ __forceinline__ float lrelu(float x) { return x > 0.f ? x : SLOPE * x; }

// ---------------- tf32 pre-rounding ----------------
__global__ void round_tf32_kernel(const float* __restrict__ in, float* __restrict__ out, int n4) {
    int i = blockIdx.x * blockDim.x + threadIdx.x;
    if (i < n4) {
        float4 v = reinterpret_cast<const float4*>(in)[i];
        v.x = wmma::__float_to_tf32(v.x);
        v.y = wmma::__float_to_tf32(v.y);
        v.z = wmma::__float_to_tf32(v.z);
        v.w = wmma::__float_to_tf32(v.w);
        reinterpret_cast<float4*>(out)[i] = v;
    }
}

// ---------------- cp.async helpers ----------------
__device__ __forceinline__ void cp_async16(void* smem, const void* g) {
    unsigned saddr = (unsigned)__cvta_generic_to_shared(smem);
    asm volatile("cp.async.cg.shared.global [%0], [%1], 16;\n" :: "r"(saddr), "l"(g));
}
__device__ __forceinline__ void cp_commit() { asm volatile("cp.async.commit_group;\n" ::: "memory"); }
__device__ __forceinline__ void cp_wait0()  { asm volatile("cp.async.wait_group 0;\n" ::: "memory"); }
__device__ __forceinline__ void cp_wait1()  { asm volatile("cp.async.wait_group 1;\n" ::: "memory"); }

// ---------------- TF32 WMMA GEMM, 3-stage cp.async pipeline ----------------
// Inputs are PRE-ROUNDED to tf32 bit patterns -> raw-bit feed is exact (truncation = identity).
#define GBM 128
#define GBK 16
#define LDA 20

template <int GBN_T>
__global__ void __launch_bounds__(256, 2)
gemm_tf32_db(const float* __restrict__ A, const float* __restrict__ B,
             float* __restrict__ C, __half* __restrict__ Ch,
             int M, int N, int K) {
    constexpr int LDB  = GBN_T + 4;
    constexpr int WN   = GBN_T / 64;
    constexpr int WNT  = WN * 16;
    constexpr int ABUF = GBM * LDA;
    constexpr int BBUF = GBK * LDB;
    constexpr int TILEBUF = ABUF + BBUF;
    constexpr int STAGE   = 64 * LDB;
    constexpr int SMEMF   = (3 * TILEBUF > STAGE) ? 3 * TILEBUF : STAGE;

    __shared__ float sbuf[SMEMF];

    const int tid  = threadIdx.x;
    const int warp = tid >> 5;
    const int wm   = warp & 1;
    const int wn   = warp >> 1;
    const int bm   = blockIdx.y * GBM;
    const int bn   = blockIdx.x * GBN_T;

    wmma::fragment<wmma::accumulator, 16, 16, 8, float> acc[4][WN];
#pragma unroll
    for (int i = 0; i < 4; i++)
#pragma unroll
        for (int j = 0; j < WN; j++) wmma::fill_fragment(acc[i][j], 0.f);

    auto load_tile = [&](int buf, int kt) {
        float* As = sbuf + buf * TILEBUF;
        float* Bs = As + ABUF;
#pragma unroll
        for (int it = 0; it < 2; it++) {
            int s = tid + 256 * it;
            int r = s >> 2, c4 = s & 3;
            int gr = bm + r, gc = kt + c4 * 4;
            float* dstp = &As[r * LDA + c4 * 4];
            if (gr < M && gc < K) cp_async16(dstp, A + (size_t)gr * K + gc);
            else *reinterpret_cast<float4*>(dstp) = make_float4(0.f, 0.f, 0.f, 0.f);
        }
        constexpr int BS = GBK * GBN_T / 4;
#pragma unroll
        for (int s = 0; s < BS; s += 256) {
            int sl = s + tid;
            int r = sl / (GBN_T / 4), c4 = sl % (GBN_T / 4);
            int gr = kt + r, gc = bn + c4 * 4;
            float* dstp = &Bs[r * LDB + c4 * 4];
            if (gr < K && gc < N) cp_async16(dstp, B + (size_t)gr * N + gc);
            else *reinterpret_cast<float4*>(dstp) = make_float4(0.f, 0.f, 0.f, 0.f);
        }
        cp_commit();
    };

    // prologue: 2 tiles in flight
    load_tile(0, 0);
    if (GBK < K) load_tile(1, GBK);

    int buf = 0;
    for (int kt = 0; kt < K; kt += GBK) {
        if (kt + GBK < K) cp_wait1(); else cp_wait0();
        __syncthreads();
        if (kt + 2 * GBK < K) load_tile((buf + 2) % 3, kt + 2 * GBK);

        const float* As = sbuf + buf * TILEBUF;
        const float* Bs = As + ABUF;
#pragma unroll
        for (int ks = 0; ks < GBK; ks += 8) {
            wmma::fragment<wmma::matrix_a, 16, 16, 8, wmma::precision::tf32, wmma::row_major> af[4];
            wmma::fragment<wmma::matrix_b, 16, 16, 8, wmma::precision::tf32, wmma::row_major> bf[WN];
#pragma unroll
            for (int i = 0; i < 4; i++)
                wmma::load_matrix_sync(af[i], &As[(wm * 64 + i * 16) * LDA + ks], LDA);
#pragma unroll
            for (int j = 0; j < WN; j++)
                wmma::load_matrix_sync(bf[j], &Bs[ks * LDB + wn * WNT + j * 16], LDB);
            // inputs pre-rounded to tf32 -> no F2F needed here
#pragma unroll
            for (int i = 0; i < 4; i++)
#pragma unroll
                for (int j = 0; j < WN; j++)
                    wmma::mma_sync(acc[i][j], af[i], bf[j], acc[i][j]);
        }
        buf = (buf + 1) % 3;
        __syncthreads();
    }

    // ---- epilogue in two 64-row halves through smem; dual-write fp32 + fp16 ----
    float* CS = sbuf;
#pragma unroll
    for (int half = 0; half < 2; half++) {
        if (wm == half) {
#pragma unroll
            for (int i = 0; i < 4; i++)
#pragma unroll
                for (int j = 0; j < WN; j++)
                    wmma::store_matrix_sync(&CS[(i * 16) * LDB + wn * WNT + j * 16],
                                            acc[i][j], LDB, wmma::mem_row_major);
        }
        __syncthreads();
        constexpr int OS = 64 * GBN_T / 4;
#pragma unroll
        for (int s = 0; s < OS; s += 256) {
            int sl = s + tid;
            int r = sl / (GBN_T / 4), c4 = sl % (GBN_T / 4);
            int gr = bm + half * 64 + r, gc = bn + c4 * 4;
            if (gr < M && gc < N) {
                float4 v = *reinterpret_cast<float4*>(&CS[r * LDB + c4 * 4]);
                *reinterpret_cast<float4*>(C + (size_t)gr * N + gc) = v;
                __half2 h0 = __floats2half2_rn(v.x, v.y);
                __half2 h1 = __floats2half2_rn(v.z, v.w);
                *reinterpret_cast<__half2*>(Ch + (size_t)gr * N + gc)     = h0;
                *reinterpret_cast<__half2*>(Ch + (size_t)gr * N + gc + 2) = h1;
            }
        }
        __syncthreads();
    }
}

// ---------------- attention scores ----------------
template <int DH>
__global__ void scores_kernel(const float* __restrict__ proj,
                              const float* __restrict__ al, const float* __restrict__ ar,
                              float* __restrict__ el, float* __restrict__ er) {
    const int n = blockIdx.x;
    const int h = threadIdx.x >> 5;
    const int lane = threadIdx.x & 31;
    const float* p = proj + (size_t)n * (4 * DH) + h * DH;
    float sl = 0.f, sr = 0.f;
    for (int c = lane; c < DH; c += 32) {
        float pv = p[c];
        sl = fmaf(pv, al[h * DH + c], sl);
        sr = fmaf(pv, ar[h * DH + c], sr);
    }
#pragma unroll
    for (int o = 16; o; o >>= 1) {
        sl += __shfl_down_sync(0xffffffffu, sl, o);
        sr += __shfl_down_sync(0xffffffffu, sr, o);
    }
    if (lane == 0) {
        el[n * 4 + h] = sl;
        er[n * 4 + h] = sr;
    }
}

// ---------------- CSR build ----------------
__global__ void count_deg_kernel(const int* __restrict__ dst) {
    int e = blockIdx.x * blockDim.x + threadIdx.x;
    if (e < NE) atomicAdd(&g_deg[dst[e]], 1);
}

__global__ void scan_kernel() {
    __shared__ int sh[1024];
    const int t = threadIdx.x;
    const int CHUNK = (NN + 1023) / 1024;
    int beg = t * CHUNK;
    int end = min(beg + CHUNK, NN);
    int s = 0;
    for (int i = beg; i < end; i++) s += g_deg[i];
    sh[t] = s;
    __syncthreads();
    for (int off = 1; off < 1024; off <<= 1) {
        int v = (t >= off) ? sh[t - off] : 0;
        __syncthreads();
        sh[t] += v;
        __syncthreads();
    }
    int run = t ? sh[t - 1] : 0;
    for (int i = beg; i < end; i++) {
        g_rowptr[i] = run;
        g_cursor[i] = run;
        run += g_deg[i];
    }
    if (t == 0) g_rowptr[NN] = sh[1023];
}

__global__ void scatter_kernel(const int* __restrict__ src, const int* __restrict__ dst) {
    int e = blockIdx.x * blockDim.x + threadIdx.x;
    if (e < NE) {
        int p = atomicAdd(&g_cursor[dst[e]], 1);
        g_srcs[p] = src[e];
    }
}

// ---------------- per-dst softmax weights: one warp per dst node ----------------
// Writes UNNORMALIZED exp(score - max) to alpha; writes inv = 1/(sum+eps) per dst/head.
__global__ void alpha_kernel(const float* __restrict__ el, const float* __restrict__ er,
                             float* __restrict__ alpha, float* __restrict__ invp) {
    const int d = blockIdx.x * 8 + (threadIdx.x >> 5);
    if (d >= NN) return;
    const int lane = threadIdx.x & 31;
    const int beg = g_rowptr[d];
    const int end = g_rowptr[d + 1];

    const float4 erd = reinterpret_cast<const float4*>(er)[d];

    float4 m = make_float4(-1e30f, -1e30f, -1e30f, -1e30f);
    for (int e = beg + lane; e < end; e += 32) {
        int sn = g_srcs[e];
        float4 l = reinterpret_cast<const float4*>(el)[sn];
        float4 v;
        v.x = lrelu(l.x + erd.x);
        v.y = lrelu(l.y + erd.y);
        v.z = lrelu(l.z + erd.z);
        v.w = lrelu(l.w + erd.w);
        reinterpret_cast<float4*>(alpha)[e] = v;
        m.x = fmaxf(m.x, v.x); m.y = fmaxf(m.y, v.y);
        m.z = fmaxf(m.z, v.z); m.w = fmaxf(m.w, v.w);
    }
#pragma unroll
    for (int o = 16; o; o >>= 1) {
        m.x = fmaxf(m.x, __shfl_xor_sync(0xffffffffu, m.x, o));
        m.y = fmaxf(m.y, __shfl_xor_sync(0xffffffffu, m.y, o));
        m.z = fmaxf(m.z, __shfl_xor_sync(0xffffffffu, m.z, o));
        m.w = fmaxf(m.w, __shfl_xor_sync(0xffffffffu, m.w, o));
    }

    float4 s = make_float4(0.f, 0.f, 0.f, 0.f);
    for (int e = beg + lane; e < end; e += 32) {
        float4 v = reinterpret_cast<float4*>(alpha)[e];
        v.x = __expf(v.x - m.x); v.y = __expf(v.y - m.y);
        v.z = __expf(v.z - m.z); v.w = __expf(v.w - m.w);
        reinterpret_cast<float4*>(alpha)[e] = v;
        s.x += v.x; s.y += v.y; s.z += v.z; s.w += v.w;
    }
#pragma unroll
    for (int o = 16; o; o >>= 1) {
        s.x += __shfl_xor_sync(0xffffffffu, s.x, o);
        s.y += __shfl_xor_sync(0xffffffffu, s.y, o);
        s.z += __shfl_xor_sync(0xffffffffu, s.z, o);
        s.w += __shfl_xor_sync(0xffffffffu, s.w, o);
    }
    if (lane == 0) {
        float4 inv;
        inv.x = 1.f / (s.x + 1e-9f); inv.y = 1.f / (s.y + 1e-9f);
        inv.z = 1.f / (s.z + 1e-9f); inv.w = 1.f / (s.w + 1e-9f);
        reinterpret_cast<float4*>(invp)[d] = inv;
    }
}

// ---------------- aggregation over fp16 proj; normalize by inv[d] at the end ----------------
// ROUND: tf32-round the written output (when it feeds the next GEMM's A operand).
template <int DH, bool ACT, bool ROUND>
__global__ void aggregate_kernel(const __half* __restrict__ projh,
                                 const float* __restrict__ alpha,
                                 const float* __restrict__ invp,
                                 const float* __restrict__ bias, float* __restrict__ out) {
    constexpr int C4 = DH;
    const int d = blockIdx.x;
    const int t = threadIdx.x;
    const int beg = g_rowptr[d];
    const int end = g_rowptr[d + 1];
    if (t >= C4) return;

    const int head = (4 * t) / DH;
    const float4 invv = reinterpret_cast<const float4*>(invp)[d];
    const float inv = (head == 0) ? invv.x : (head == 1) ? invv.y : (head == 2) ? invv.z : invv.w;

    float4 acc = make_float4(0.f, 0.f, 0.f, 0.f);
#pragma unroll 2
    for (int e = beg; e < end; e++) {
        int sn = g_srcs[e];
        float4 a = reinterpret_cast<const float4*>(alpha)[e];   // broadcast
        float w = (head == 0) ? a.x : (head == 1) ? a.y : (head == 2) ? a.z : a.w;
        const __half2* ph =
            reinterpret_cast<const __half2*>(projh + (size_t)sn * (4 * DH)) + 2 * t;
        float2 p0 = __half22float2(ph[0]);
        float2 p1 = __half22float2(ph[1]);
        acc.x = fmaf(w, p0.x, acc.x);
        acc.y = fmaf(w, p0.y, acc.y);
        acc.z = fmaf(w, p1.x, acc.z);
        acc.w = fmaf(w, p1.y, acc.w);
    }
    float4 b = reinterpret_cast<const float4*>(bias)[t];
    acc.x = fmaf(acc.x, inv, b.x);
    acc.y = fmaf(acc.y, inv, b.y);
    acc.z = fmaf(acc.z, inv, b.z);
    acc.w = fmaf(acc.w, inv, b.w);
    if (ACT) {
        acc.x = lrelu(acc.x); acc.y = lrelu(acc.y);
        acc.z = lrelu(acc.z); acc.w = lrelu(acc.w);
    }
    if (ROUND) {
        acc.x = wmma::__float_to_tf32(acc.x);
        acc.y = wmma::__float_to_tf32(acc.y);
        acc.z = wmma::__float_to_tf32(acc.z);
        acc.w = wmma::__float_to_tf32(acc.w);
    }
    reinterpret_cast<float4*>(out)[(size_t)d * C4 + t] = acc;
}

// ---------------- launch ----------------
extern "C" void kernel_launch(void* const* d_in, const int* in_sizes, int n_in,
                              void* d_out, int out_size) {
    const float* x   = (const float*)d_in[0];
    const float* W1  = (const float*)d_in[1];
    const float* al1 = (const float*)d_in[2];
    const float* ar1 = (const float*)d_in[3];
    const float* b1  = (const float*)d_in[4];
    const float* W2  = (const float*)d_in[5];
    const float* al2 = (const float*)d_in[6];
    const float* ar2 = (const float*)d_in[7];
    const float* b2  = (const float*)d_in[8];
    const int*   src = (const int*)d_in[9];
    const int*   dst = (const int*)d_in[10];
    float* out = (float*)d_out;

    float *proj1, *h1, *proj2, *el1, *er1, *el2, *er2, *alpha, *invp, *degp;
    float *xr, *w1r, *w2r;
    __half *projh1, *projh2;
    cudaGetSymbolAddress((void**)&proj1, g_proj1);
    cudaGetSymbolAddress((void**)&h1, g_h1);
    cudaGetSymbolAddress((void**)&proj2, g_proj2);
    cudaGetSymbolAddress((void**)&xr, g_xr);
    cudaGetSymbolAddress((void**)&w1r, g_w1r);
    cudaGetSymbolAddress((void**)&w2r, g_w2r);
    cudaGetSymbolAddress((void**)&projh1, g_projh1);
    cudaGetSymbolAddress((void**)&projh2, g_projh2);
    cudaGetSymbolAddress((void**)&el1, g_el1);
    cudaGetSymbolAddress((void**)&er1, g_er1);
    cudaGetSymbolAddress((void**)&el2, g_el2);
    cudaGetSymbolAddress((void**)&er2, g_er2);
    cudaGetSymbolAddress((void**)&alpha, g_alpha);
    cudaGetSymbolAddress((void**)&invp, g_inv);
    cudaGetSymbolAddress((void**)&degp, g_deg);

    // pre-round GEMM inputs to tf32 bit patterns (counts all divisible by 4)
    round_tf32_kernel<<<(NN * 300 / 4 + 255) / 256, 256>>>(x, xr, NN * 300 / 4);
    round_tf32_kernel<<<(300 * 400 / 4 + 255) / 256, 256>>>(W1, w1r, 300 * 400 / 4);
    round_tf32_kernel<<<(400 * 512 / 4 + 255) / 256, 256>>>(W2, w2r, 400 * 512 / 4);

    // CSR build
    cudaMemsetAsync(degp, 0, NN * sizeof(int));
    count_deg_kernel<<<(NE + 255) / 256, 256>>>(dst);
    scan_kernel<<<1, 1024>>>();
    scatter_kernel<<<(NE + 255) / 256, 256>>>(src, dst);

    const int ABLK = (NN + 7) / 8;

    // layer 1
    {
        dim3 grid((400 + 63) / 64, (NN + GBM - 1) / GBM);
        gemm_tf32_db<64><<<grid, 256>>>(xr, w1r, proj1, projh1, NN, 400, 300);
    }
    scores_kernel<100><<<NN, 128>>>(proj1, al1, ar1, el1, er1);
    alpha_kernel<<<ABLK, 256>>>(el1, er1, alpha, invp);
    aggregate_kernel<100, true, true><<<NN, 128>>>(projh1, alpha, invp, b1, h1);

    // layer 2
    {
        dim3 grid(512 / 128, (NN + GBM - 1) / GBM);
        gemm_tf32_db<128><<<grid, 256>>>(h1, w2r, proj2, projh2, NN, 512, 400);
    }
    scores_kernel<128><<<NN, 128>>>(proj2, al2, ar2, el2, er2);
    alpha_kernel<<<ABLK, 256>>>(el2, er2, alpha, invp);
    aggregate_kernel<128, false, false><<<NN, 128>>>(projh2, alpha, invp, b2, out);
}

// round 11
// speedup vs baseline: 3.2654x; 1.4386x over previous
#include <cuda_runtime.h>
#include <cuda_fp16.h>
#include <mma.h>
#include <math.h>

using namespace nvcuda;

#define NN 50000
#define NE 800000
#define NHEADS 4
#define SLOPE 0.2f
#define XLD 304              // padded fp16 row stride for x (608B, 16B-aligned)

// ---------------- scratch (static device globals; no allocation) ----------------
__device__ float  g_proj1[NN * 400];       // 80 MB (fp32, for scores)
__device__ float  g_proj2[NN * 512];       // 102.4 MB (fp32, for scores)
__device__ __half g_projh1[NN * 400];      // 40 MB (fp16 gather copy)
__device__ __half g_projh2[NN * 512];      // 51.2 MB
__device__ __half g_xh[NN * XLD];          // 30.4 MB (fp16 x, padded rows; pad cols stay 0)
__device__ __half g_w1h[300 * 400];
__device__ __half g_w2h[400 * 512];
__device__ __half g_h1h[NN * 400];         // 40 MB (fp16 hidden, GEMM2 A operand)
__device__ float  g_el1[NN * NHEADS];
__device__ float  g_er1[NN * NHEADS];
__device__ float  g_el2[NN * NHEADS];
__device__ float  g_er2[NN * NHEADS];
__device__ float  g_alpha[NE * 4];         // per-edge UNNORMALIZED exp weights
__device__ float  g_inv[NN * 4];           // per-dst, per-head 1/(sum+eps)
__device__ int    g_deg[NN];
__device__ int    g_rowptr[NN + 1];
__device__ int    g_cursor[NN];
__device__ int    g_srcs[NE];

__device__ __forceinline__ float lrelu(float x) { return x > 0.f ? x : SLOPE * x; }

// ---------------- fp32 -> fp16 converts ----------------
__global__ void f2h_kernel(const float* __restrict__ in, __half* __restrict__ out, int n4) {
    int i = blockIdx.x * blockDim.x + threadIdx.x;
    if (i < n4) {
        float4 v = reinterpret_cast<const float4*>(in)[i];
        reinterpret_cast<__half2*>(out)[2 * i]     = __floats2half2_rn(v.x, v.y);
        reinterpret_cast<__half2*>(out)[2 * i + 1] = __floats2half2_rn(v.z, v.w);
    }
}

// x: [NN,300] fp32 -> [NN,XLD] fp16 (row-padded). 75 float4-quads per row.
__global__ void f2h_pad_kernel(const float* __restrict__ in, __half* __restrict__ out) {
    int i = blockIdx.x * blockDim.x + threadIdx.x;
    if (i < NN * 75) {
        int row = i / 75, q = i % 75;
        float4 v = *reinterpret_cast<const float4*>(in + (size_t)row * 300 + q * 4);
        __half* o = out + (size_t)row * XLD + q * 4;
        reinterpret_cast<__half2*>(o)[0] = __floats2half2_rn(v.x, v.y);
        reinterpret_cast<__half2*>(o)[1] = __floats2half2_rn(v.z, v.w);
    }
}

// ---------------- cp.async helpers ----------------
__device__ __forceinline__ void cp_async16(void* smem, const void* g) {
    unsigned saddr = (unsigned)__cvta_generic_to_shared(smem);
    asm volatile("cp.async.cg.shared.global [%0], [%1], 16;\n" :: "r"(saddr), "l"(g));
}
__device__ __forceinline__ void cp_commit() { asm volatile("cp.async.commit_group;\n" ::: "memory"); }
__device__ __forceinline__ void cp_wait0()  { asm volatile("cp.async.wait_group 0;\n" ::: "memory"); }
__device__ __forceinline__ void cp_wait1()  { asm volatile("cp.async.wait_group 1;\n" ::: "memory"); }

// ---------------- FP16 WMMA GEMM (fp32 accumulate), 3-stage cp.async ----------------
// Block tile 128x64x32. 8 warps: 2 (M, x64) x 4 (N, x16). m16n16k16 frags.
// lda = A global row stride in halves (16B-aligned rows required).
#define GBM 128
#define GBN 64
#define GBK 32
#define LDA 40            // smem half stride (mult of 8)
#define LDB 72            // smem half stride (GBN+8)
#define LDC 68            // float staging stride
#define ABUF (GBM * LDA)
#define BBUF (GBK * LDB)
#define TILEBUF (ABUF + BBUF)
#define SMEM_BYTES 44544  // 3 * TILEBUF * 2 (> 64*LDC*4)

__global__ void __launch_bounds__(256, 2)
gemm_f16(const __half* __restrict__ A, const __half* __restrict__ B,
         float* __restrict__ C, __half* __restrict__ Ch,
         int M, int N, int K, int lda) {
    __shared__ __align__(16) char smem_raw[SMEM_BYTES];
    __half* sbuf = reinterpret_cast<__half*>(smem_raw);

    const int tid  = threadIdx.x;
    const int warp = tid >> 5;
    const int wm   = warp & 1;
    const int wn   = warp >> 1;
    const int bm   = blockIdx.y * GBM;
    const int bn   = blockIdx.x * GBN;

    wmma::fragment<wmma::accumulator, 16, 16, 16, float> acc[4];
#pragma unroll
    for (int i = 0; i < 4; i++) wmma::fill_fragment(acc[i], 0.f);

    auto load_tile = [&](int buf, int kt) {
        __half* As = sbuf + buf * TILEBUF;
        __half* Bs = As + ABUF;
        // A: 128 rows x 4 chunks (8 halves) = 512 chunks, 2/thread.
        // Chunk may cross K into the zero pad (pad cols are zero-initialized) — safe.
#pragma unroll
        for (int it = 0; it < 2; it++) {
            int s = tid + 256 * it;
            int r = s >> 2, c8 = s & 3;
            int gr = bm + r, gc = kt + c8 * 8;
            __half* dstp = &As[r * LDA + c8 * 8];
            if (gr < M && gc < K) cp_async16(dstp, A + (size_t)gr * lda + gc);
            else *reinterpret_cast<float4*>(dstp) = make_float4(0.f, 0.f, 0.f, 0.f);
        }
        // B: 32 rows x 8 chunks = 256 chunks, 1/thread
        {
            int r = tid >> 3, c8 = tid & 7;
            int gr = kt + r, gc = bn + c8 * 8;
            __half* dstp = &Bs[r * LDB + c8 * 8];
            if (gr < K && gc < N) cp_async16(dstp, B + (size_t)gr * N + gc);
            else *reinterpret_cast<float4*>(dstp) = make_float4(0.f, 0.f, 0.f, 0.f);
        }
        cp_commit();
    };

    load_tile(0, 0);
    if (GBK < K) load_tile(1, GBK);

    int buf = 0;
    for (int kt = 0; kt < K; kt += GBK) {
        if (kt + GBK < K) cp_wait1(); else cp_wait0();
        __syncthreads();
        if (kt + 2 * GBK < K) load_tile((buf + 2) % 3, kt + 2 * GBK);

        const __half* As = sbuf + buf * TILEBUF;
        const __half* Bs = As + ABUF;
#pragma unroll
        for (int ks = 0; ks < GBK; ks += 16) {
            wmma::fragment<wmma::matrix_a, 16, 16, 16, __half, wmma::row_major> af[4];
            wmma::fragment<wmma::matrix_b, 16, 16, 16, __half, wmma::row_major> bf;
#pragma unroll
            for (int i = 0; i < 4; i++)
                wmma::load_matrix_sync(af[i], &As[(wm * 64 + i * 16) * LDA + ks], LDA);
            wmma::load_matrix_sync(bf, &Bs[ks * LDB + wn * 16], LDB);
#pragma unroll
            for (int i = 0; i < 4; i++)
                wmma::mma_sync(acc[i], af[i], bf, acc[i]);
        }
        buf = (buf + 1) % 3;
        __syncthreads();
    }

    // ---- epilogue: two 64-row halves through float staging; dual-write fp32 + fp16 ----
    float* CS = reinterpret_cast<float*>(smem_raw);
#pragma unroll
    for (int half = 0; half < 2; half++) {
        if (wm == half) {
#pragma unroll
            for (int i = 0; i < 4; i++)
                wmma::store_matrix_sync(&CS[(i * 16) * LDC + wn * 16],
                                        acc[i], LDC, wmma::mem_row_major);
        }
        __syncthreads();
#pragma unroll
        for (int it = 0; it < 4; it++) {
            int sl = tid + 256 * it;
            int r = sl >> 4, c4 = sl & 15;
            int gr = bm + half * 64 + r, gc = bn + c4 * 4;
            if (gr < M && gc < N) {
                float4 v = *reinterpret_cast<float4*>(&CS[r * LDC + c4 * 4]);
                *reinterpret_cast<float4*>(C + (size_t)gr * N + gc) = v;
                *reinterpret_cast<__half2*>(Ch + (size_t)gr * N + gc)     = __floats2half2_rn(v.x, v.y);
                *reinterpret_cast<__half2*>(Ch + (size_t)gr * N + gc + 2) = __floats2half2_rn(v.z, v.w);
            }
        }
        __syncthreads();
    }
}

// ---------------- attention scores ----------------
template <int DH>
__global__ void scores_kernel(const float* __restrict__ proj,
                              const float* __restrict__ al, const float* __restrict__ ar,
                              float* __restrict__ el, float* __restrict__ er) {
    const int n = blockIdx.x;
    const int h = threadIdx.x >> 5;
    const int lane = threadIdx.x & 31;
    const float* p = proj + (size_t)n * (4 * DH) + h * DH;
    float sl = 0.f, sr = 0.f;
    for (int c = lane; c < DH; c += 32) {
        float pv = p[c];
        sl = fmaf(pv, al[h * DH + c], sl);
        sr = fmaf(pv, ar[h * DH + c], sr);
    }
#pragma unroll
    for (int o = 16; o; o >>= 1) {
        sl += __shfl_down_sync(0xffffffffu, sl, o);
        sr += __shfl_down_sync(0xffffffffu, sr, o);
    }
    if (lane == 0) {
        el[n * 4 + h] = sl;
        er[n * 4 + h] = sr;
    }
}

// ---------------- CSR build ----------------
__global__ void count_deg_kernel(const int* __restrict__ dst) {
    int e = blockIdx.x * blockDim.x + threadIdx.x;
    if (e < NE) atomicAdd(&g_deg[dst[e]], 1);
}

__global__ void scan_kernel() {
    __shared__ int sh[1024];
    const int t = threadIdx.x;
    const int CHUNK = (NN + 1023) / 1024;
    int beg = t * CHUNK;
    int end = min(beg + CHUNK, NN);
    int s = 0;
    for (int i = beg; i < end; i++) s += g_deg[i];
    sh[t] = s;
    __syncthreads();
    for (int off = 1; off < 1024; off <<= 1) {
        int v = (t >= off) ? sh[t - off] : 0;
        __syncthreads();
        sh[t] += v;
        __syncthreads();
    }
    int run = t ? sh[t - 1] : 0;
    for (int i = beg; i < end; i++) {
        g_rowptr[i] = run;
        g_cursor[i] = run;
        run += g_deg[i];
    }
    if (t == 0) g_rowptr[NN] = sh[1023];
}

__global__ void scatter_kernel(const int* __restrict__ src, const int* __restrict__ dst) {
    int e = blockIdx.x * blockDim.x + threadIdx.x;
    if (e < NE) {
        int p = atomicAdd(&g_cursor[dst[e]], 1);
        g_srcs[p] = src[e];
    }
}

// ---------------- per-dst softmax weights: one warp per dst node ----------------
__global__ void alpha_kernel(const float* __restrict__ el, const float* __restrict__ er,
                             float* __restrict__ alpha, float* __restrict__ invp) {
    const int d = blockIdx.x * 8 + (threadIdx.x >> 5);
    if (d >= NN) return;
    const int lane = threadIdx.x & 31;
    const int beg = g_rowptr[d];
    const int end = g_rowptr[d + 1];

    const float4 erd = reinterpret_cast<const float4*>(er)[d];

    float4 m = make_float4(-1e30f, -1e30f, -1e30f, -1e30f);
    for (int e = beg + lane; e < end; e += 32) {
        int sn = g_srcs[e];
        float4 l = reinterpret_cast<const float4*>(el)[sn];
        float4 v;
        v.x = lrelu(l.x + erd.x);
        v.y = lrelu(l.y + erd.y);
        v.z = lrelu(l.z + erd.z);
        v.w = lrelu(l.w + erd.w);
        reinterpret_cast<float4*>(alpha)[e] = v;
        m.x = fmaxf(m.x, v.x); m.y = fmaxf(m.y, v.y);
        m.z = fmaxf(m.z, v.z); m.w = fmaxf(m.w, v.w);
    }
#pragma unroll
    for (int o = 16; o; o >>= 1) {
        m.x = fmaxf(m.x, __shfl_xor_sync(0xffffffffu, m.x, o));
        m.y = fmaxf(m.y, __shfl_xor_sync(0xffffffffu, m.y, o));
        m.z = fmaxf(m.z, __shfl_xor_sync(0xffffffffu, m.z, o));
        m.w = fmaxf(m.w, __shfl_xor_sync(0xffffffffu, m.w, o));
    }

    float4 s = make_float4(0.f, 0.f, 0.f, 0.f);
    for (int e = beg + lane; e < end; e += 32) {
        float4 v = reinterpret_cast<float4*>(alpha)[e];
        v.x = __expf(v.x - m.x); v.y = __expf(v.y - m.y);
        v.z = __expf(v.z - m.z); v.w = __expf(v.w - m.w);
        reinterpret_cast<float4*>(alpha)[e] = v;
        s.x += v.x; s.y += v.y; s.z += v.z; s.w += v.w;
    }
#pragma unroll
    for (int o = 16; o; o >>= 1) {
        s.x += __shfl_xor_sync(0xffffffffu, s.x, o);
        s.y += __shfl_xor_sync(0xffffffffu, s.y, o);
        s.z += __shfl_xor_sync(0xffffffffu, s.z, o);
        s.w += __shfl_xor_sync(0xffffffffu, s.w, o);
    }
    if (lane == 0) {
        float4 inv;
        inv.x = 1.f / (s.x + 1e-9f); inv.y = 1.f / (s.y + 1e-9f);
        inv.z = 1.f / (s.z + 1e-9f); inv.w = 1.f / (s.w + 1e-9f);
        reinterpret_cast<float4*>(invp)[d] = inv;
    }
}

// ---------------- aggregation (fp16 gather); OUT_HALF: write fp16 (feeds GEMM2) ----------------
template <int DH, bool ACT, bool OUT_HALF>
__global__ void aggregate_kernel(const __half* __restrict__ projh,
                                 const float* __restrict__ alpha,
                                 const float* __restrict__ invp,
                                 const float* __restrict__ bias, void* __restrict__ outp) {
    constexpr int C4 = DH;
    const int d = blockIdx.x;
    const int t = threadIdx.x;
    const int beg = g_rowptr[d];
    const int end = g_rowptr[d + 1];
    if (t >= C4) return;

    const int head = (4 * t) / DH;
    const float4 invv = reinterpret_cast<const float4*>(invp)[d];
    const float inv = (head == 0) ? invv.x : (head == 1) ? invv.y : (head == 2) ? invv.z : invv.w;

    float4 acc = make_float4(0.f, 0.f, 0.f, 0.f);
#pragma unroll 2
    for (int e = beg; e < end; e++) {
        int sn = g_srcs[e];
        float4 a = reinterpret_cast<const float4*>(alpha)[e];   // broadcast
        float w = (head == 0) ? a.x : (head == 1) ? a.y : (head == 2) ? a.z : a.w;
        const __half2* ph =
            reinterpret_cast<const __half2*>(projh + (size_t)sn * (4 * DH)) + 2 * t;
        float2 p0 = __half22float2(ph[0]);
        float2 p1 = __half22float2(ph[1]);
        acc.x = fmaf(w, p0.x, acc.x);
        acc.y = fmaf(w, p0.y, acc.y);
        acc.z = fmaf(w, p1.x, acc.z);
        acc.w = fmaf(w, p1.y, acc.w);
    }
    float4 b = reinterpret_cast<const float4*>(bias)[t];
    acc.x = fmaf(acc.x, inv, b.x);
    acc.y = fmaf(acc.y, inv, b.y);
    acc.z = fmaf(acc.z, inv, b.z);
    acc.w = fmaf(acc.w, inv, b.w);
    if (ACT) {
        acc.x = lrelu(acc.x); acc.y = lrelu(acc.y);
        acc.z = lrelu(acc.z); acc.w = lrelu(acc.w);
    }
    if (OUT_HALF) {
        __half2* o = reinterpret_cast<__half2*>((__half*)outp + (size_t)d * (4 * DH)) + 2 * t;
        o[0] = __floats2half2_rn(acc.x, acc.y);
        o[1] = __floats2half2_rn(acc.z, acc.w);
    } else {
        reinterpret_cast<float4*>((float*)outp)[(size_t)d * C4 + t] = acc;
    }
}

// ---------------- launch ----------------
extern "C" void kernel_launch(void* const* d_in, const int* in_sizes, int n_in,
                              void* d_out, int out_size) {
    const float* x   = (const float*)d_in[0];
    const float* W1  = (const float*)d_in[1];
    const float* al1 = (const float*)d_in[2];
    const float* ar1 = (const float*)d_in[3];
    const float* b1  = (const float*)d_in[4];
    const float* W2  = (const float*)d_in[5];
    const float* al2 = (const float*)d_in[6];
    const float* ar2 = (const float*)d_in[7];
    const float* b2  = (const float*)d_in[8];
    const int*   src = (const int*)d_in[9];
    const int*   dst = (const int*)d_in[10];
    float* out = (float*)d_out;

    float *proj1, *proj2, *el1, *er1, *el2, *er2, *alpha, *invp, *degp;
    __half *projh1, *projh2, *xh, *w1h, *w2h, *h1h;
    cudaGetSymbolAddress((void**)&proj1, g_proj1);
    cudaGetSymbolAddress((void**)&proj2, g_proj2);
    cudaGetSymbolAddress((void**)&projh1, g_projh1);
    cudaGetSymbolAddress((void**)&projh2, g_projh2);
    cudaGetSymbolAddress((void**)&xh, g_xh);
    cudaGetSymbolAddress((void**)&w1h, g_w1h);
    cudaGetSymbolAddress((void**)&w2h, g_w2h);
    cudaGetSymbolAddress((void**)&h1h, g_h1h);
    cudaGetSymbolAddress((void**)&el1, g_el1);
    cudaGetSymbolAddress((void**)&er1, g_er1);
    cudaGetSymbolAddress((void**)&el2, g_el2);
    cudaGetSymbolAddress((void**)&er2, g_er2);
    cudaGetSymbolAddress((void**)&alpha, g_alpha);
    cudaGetSymbolAddress((void**)&invp, g_inv);
    cudaGetSymbolAddress((void**)&degp, g_deg);

    // fp32 -> fp16 conversions (RN)
    f2h_pad_kernel<<<(NN * 75 + 255) / 256, 256>>>(x, xh);
    f2h_kernel<<<(300 * 400 / 4 + 255) / 256, 256>>>(W1, w1h, 300 * 400 / 4);
    f2h_kernel<<<(400 * 512 / 4 + 255) / 256, 256>>>(W2, w2h, 400 * 512 / 4);

    // CSR build
    cudaMemsetAsync(degp, 0, NN * sizeof(int));
    count_deg_kernel<<<(NE + 255) / 256, 256>>>(dst);
    scan_kernel<<<1, 1024>>>();
    scatter_kernel<<<(NE + 255) / 256, 256>>>(src, dst);

    const int ABLK = (NN + 7) / 8;
    const int GR = (NN + GBM - 1) / GBM;

    // layer 1: GEMM [50000,300]x[300,400]  (A stride = XLD)
    {
        dim3 grid((400 + GBN - 1) / GBN, GR);
        gemm_f16<<<grid, 256>>>(xh, w1h, proj1, projh1, NN, 400, 300, XLD);
    }
    scores_kernel<100><<<NN, 128>>>(proj1, al1, ar1, el1, er1);
    alpha_kernel<<<ABLK, 256>>>(el1, er1, alpha, invp);
    aggregate_kernel<100, true, true><<<NN, 128>>>(projh1, alpha, invp, b1, h1h);

    // layer 2: GEMM [50000,400]x[400,512]  (A stride = 400)
    {
        dim3 grid((512 + GBN - 1) / GBN, GR);
        gemm_f16<<<grid, 256>>>(h1h, w2h, proj2, projh2, NN, 512, 400, 400);
    }
    scores_kernel<128><<<NN, 128>>>(proj2, al2, ar2, el2, er2);
    alpha_kernel<<<ABLK, 256>>>(el2, er2, alpha, invp);
    aggregate_kernel<128, false, false><<<NN, 128>>>(projh2, alpha, invp, b2, out);
}

// round 12
// speedup vs baseline: 3.3305x; 1.0200x over previous
#include <cuda_runtime.h>
#include <cuda_fp16.h>
#include <mma.h>
#include <math.h>

using namespace nvcuda;

#define NN 50000
#define NE 800000
#define NHEADS 4
#define SLOPE 0.2f
#define XLD 304              // padded fp16 row stride for x (608B, 16B-aligned)

// ---------------- scratch (static device globals; no allocation) ----------------
__device__ __half g_projh1[NN * 400];      // 40 MB (fp16 gather source, layer1)
__device__ __half g_projh2[NN * 512];      // 51.2 MB (layer2)
__device__ __half g_xh[NN * XLD];          // 30.4 MB (fp16 x, padded rows; pad cols stay 0)
__device__ __half g_w1h[300 * 400];
__device__ __half g_w2h[400 * 512];
__device__ __half g_h1h[NN * 400];         // 40 MB (fp16 hidden, GEMM2 A operand + scores2 input)
__device__ float  g_wl1[300 * 8];          // [k][j]: j<4 -> W1·al1 ; j>=4 -> W1·ar1
__device__ float  g_wl2[400 * 8];
__device__ float  g_el1[NN * NHEADS];
__device__ float  g_er1[NN * NHEADS];
__device__ float  g_el2[NN * NHEADS];
__device__ float  g_er2[NN * NHEADS];
__device__ float  g_alpha[NE * 4];         // per-edge UNNORMALIZED exp weights
__device__ float  g_inv[NN * 4];           // per-dst, per-head 1/(sum+eps)
__device__ int    g_deg[NN];
__device__ int    g_rowptr[NN + 1];
__device__ int    g_cursor[NN];
__device__ int    g_srcs[NE];

__device__ __forceinline__ float lrelu(float x) { return x > 0.f ? x : SLOPE * x; }

// ---------------- fp32 -> fp16 converts ----------------
__global__ void f2h_kernel(const float* __restrict__ in, __half* __restrict__ out, int n4) {
    int i = blockIdx.x * blockDim.x + threadIdx.x;
    if (i < n4) {
        float4 v = reinterpret_cast<const float4*>(in)[i];
        reinterpret_cast<__half2*>(out)[2 * i]     = __floats2half2_rn(v.x, v.y);
        reinterpret_cast<__half2*>(out)[2 * i + 1] = __floats2half2_rn(v.z, v.w);
    }
}

// x: [NN,300] fp32 -> [NN,XLD] fp16 (row-padded). 75 float4-quads per row.
__global__ void f2h_pad_kernel(const float* __restrict__ in, __half* __restrict__ out) {
    int i = blockIdx.x * blockDim.x + threadIdx.x;
    if (i < NN * 75) {
        int row = i / 75, q = i % 75;
        float4 v = *reinterpret_cast<const float4*>(in + (size_t)row * 300 + q * 4);
        __half* o = out + (size_t)row * XLD + q * 4;
        reinterpret_cast<__half2*>(o)[0] = __floats2half2_rn(v.x, v.y);
        reinterpret_cast<__half2*>(o)[1] = __floats2half2_rn(v.z, v.w);
    }
}

// ---------------- Wl = [W·al ; W·ar] precompute: Wl[k*8+j] ----------------
template <int K, int DH>
__global__ void make_wl_kernel(const float* __restrict__ W, const float* __restrict__ al,
                               const float* __restrict__ ar, float* __restrict__ Wl) {
    int idx = blockIdx.x * blockDim.x + threadIdx.x;
    if (idx < K * 8) {
        int k = idx >> 3, j = idx & 7;
        const float* av = (j < 4) ? (al + j * DH) : (ar + (j - 4) * DH);
        const float* wrow = W + (size_t)k * (4 * DH) + (j & 3) * DH;
        float s = 0.f;
        for (int d = 0; d < DH; d++) s = fmaf(wrow[d], av[d], s);
        Wl[idx] = s;
    }
}

// ---------------- scores via skinny GEMM: el/er[n,j] = X[n,:] @ Wl[:,j] ----------------
// one warp per node; Wl cached in smem with stride-9 pad (conflict-free).
template <int K, typename T>
__global__ void scores_w_kernel(const T* __restrict__ X, int ldx,
                                const float* __restrict__ Wl,
                                float* __restrict__ el, float* __restrict__ er) {
    __shared__ float sw[K][9];
    const int tid = threadIdx.x;
    for (int i = tid; i < K * 8; i += 256) sw[i >> 3][i & 7] = Wl[i];
    __syncthreads();
    const int warp = tid >> 5, lane = tid & 31;
    const int n = blockIdx.x * 8 + warp;
    if (n >= NN) return;
    const T* xrow = X + (size_t)n * ldx;
    float a[8] = {0.f, 0.f, 0.f, 0.f, 0.f, 0.f, 0.f, 0.f};
    for (int k = lane; k < K; k += 32) {
        float xv = (float)xrow[k];
#pragma unroll
        for (int j = 0; j < 8; j++) a[j] = fmaf(xv, sw[k][j], a[j]);
    }
#pragma unroll
    for (int j = 0; j < 8; j++)
#pragma unroll
        for (int o = 16; o; o >>= 1) a[j] += __shfl_xor_sync(0xffffffffu, a[j], o);
    if (lane == 0) {
        reinterpret_cast<float4*>(el)[n] = make_float4(a[0], a[1], a[2], a[3]);
        reinterpret_cast<float4*>(er)[n] = make_float4(a[4], a[5], a[6], a[7]);
    }
}

// ---------------- cp.async helpers ----------------
__device__ __forceinline__ void cp_async16(void* smem, const void* g) {
    unsigned saddr = (unsigned)__cvta_generic_to_shared(smem);
    asm volatile("cp.async.cg.shared.global [%0], [%1], 16;\n" :: "r"(saddr), "l"(g));
}
__device__ __forceinline__ void cp_commit() { asm volatile("cp.async.commit_group;\n" ::: "memory"); }
__device__ __forceinline__ void cp_wait0()  { asm volatile("cp.async.wait_group 0;\n" ::: "memory"); }
__device__ __forceinline__ void cp_wait1()  { asm volatile("cp.async.wait_group 1;\n" ::: "memory"); }

// ---------------- FP16 WMMA GEMM (fp32 accumulate), 3-stage cp.async ----------------
// Output: fp16 ONLY (scores are computed separately from folded Wl).
#define GBM 128
#define GBN 64
#define GBK 32
#define LDA 40
#define LDB 72
#define LDC 68
#define ABUF (GBM * LDA)
#define BBUF (GBK * LDB)
#define TILEBUF (ABUF + BBUF)
#define SMEM_BYTES 44544

__global__ void __launch_bounds__(256, 2)
gemm_f16(const __half* __restrict__ A, const __half* __restrict__ B,
         __half* __restrict__ Ch, int M, int N, int K, int lda) {
    __shared__ __align__(16) char smem_raw[SMEM_BYTES];
    __half* sbuf = reinterpret_cast<__half*>(smem_raw);

    const int tid  = threadIdx.x;
    const int warp = tid >> 5;
    const int wm   = warp & 1;
    const int wn   = warp >> 1;
    const int bm   = blockIdx.y * GBM;
    const int bn   = blockIdx.x * GBN;

    wmma::fragment<wmma::accumulator, 16, 16, 16, float> acc[4];
#pragma unroll
    for (int i = 0; i < 4; i++) wmma::fill_fragment(acc[i], 0.f);

    auto load_tile = [&](int buf, int kt) {
        __half* As = sbuf + buf * TILEBUF;
        __half* Bs = As + ABUF;
#pragma unroll
        for (int it = 0; it < 2; it++) {
            int s = tid + 256 * it;
            int r = s >> 2, c8 = s & 3;
            int gr = bm + r, gc = kt + c8 * 8;
            __half* dstp = &As[r * LDA + c8 * 8];
            if (gr < M && gc < K) cp_async16(dstp, A + (size_t)gr * lda + gc);
            else *reinterpret_cast<float4*>(dstp) = make_float4(0.f, 0.f, 0.f, 0.f);
        }
        {
            int r = tid >> 3, c8 = tid & 7;
            int gr = kt + r, gc = bn + c8 * 8;
            __half* dstp = &Bs[r * LDB + c8 * 8];
            if (gr < K && gc < N) cp_async16(dstp, B + (size_t)gr * N + gc);
            else *reinterpret_cast<float4*>(dstp) = make_float4(0.f, 0.f, 0.f, 0.f);
        }
        cp_commit();
    };

    load_tile(0, 0);
    if (GBK < K) load_tile(1, GBK);

    int buf = 0;
    for (int kt = 0; kt < K; kt += GBK) {
        if (kt + GBK < K) cp_wait1(); else cp_wait0();
        __syncthreads();
        if (kt + 2 * GBK < K) load_tile((buf + 2) % 3, kt + 2 * GBK);

        const __half* As = sbuf + buf * TILEBUF;
        const __half* Bs = As + ABUF;
#pragma unroll
        for (int ks = 0; ks < GBK; ks += 16) {
            wmma::fragment<wmma::matrix_a, 16, 16, 16, __half, wmma::row_major> af[4];
            wmma::fragment<wmma::matrix_b, 16, 16, 16, __half, wmma::row_major> bf;
#pragma unroll
            for (int i = 0; i < 4; i++)
                wmma::load_matrix_sync(af[i], &As[(wm * 64 + i * 16) * LDA + ks], LDA);
            wmma::load_matrix_sync(bf, &Bs[ks * LDB + wn * 16], LDB);
#pragma unroll
            for (int i = 0; i < 4; i++)
                wmma::mma_sync(acc[i], af[i], bf, acc[i]);
        }
        buf = (buf + 1) % 3;
        __syncthreads();
    }

    // ---- epilogue: two 64-row halves through float staging; fp16-only output ----
    float* CS = reinterpret_cast<float*>(smem_raw);
#pragma unroll
    for (int half = 0; half < 2; half++) {
        if (wm == half) {
#pragma unroll
            for (int i = 0; i < 4; i++)
                wmma::store_matrix_sync(&CS[(i * 16) * LDC + wn * 16],
                                        acc[i], LDC, wmma::mem_row_major);
        }
        __syncthreads();
#pragma unroll
        for (int it = 0; it < 4; it++) {
            int sl = tid + 256 * it;
            int r = sl >> 4, c4 = sl & 15;
            int gr = bm + half * 64 + r, gc = bn + c4 * 4;
            if (gr < M && gc < N) {
                float4 v = *reinterpret_cast<float4*>(&CS[r * LDC + c4 * 4]);
                *reinterpret_cast<__half2*>(Ch + (size_t)gr * N + gc)     = __floats2half2_rn(v.x, v.y);
                *reinterpret_cast<__half2*>(Ch + (size_t)gr * N + gc + 2) = __floats2half2_rn(v.z, v.w);
            }
        }
        __syncthreads();
    }
}

// ---------------- CSR build ----------------
__global__ void count_deg_kernel(const int* __restrict__ dst) {
    int e = blockIdx.x * blockDim.x + threadIdx.x;
    if (e < NE) atomicAdd(&g_deg[dst[e]], 1);
}

__global__ void scan_kernel() {
    __shared__ int sh[1024];
    const int t = threadIdx.x;
    const int CHUNK = (NN + 1023) / 1024;
    int beg = t * CHUNK;
    int end = min(beg + CHUNK, NN);
    int s = 0;
    for (int i = beg; i < end; i++) s += g_deg[i];
    sh[t] = s;
    __syncthreads();
    for (int off = 1; off < 1024; off <<= 1) {
        int v = (t >= off) ? sh[t - off] : 0;
        __syncthreads();
        sh[t] += v;
        __syncthreads();
    }
    int run = t ? sh[t - 1] : 0;
    for (int i = beg; i < end; i++) {
        g_rowptr[i] = run;
        g_cursor[i] = run;
        run += g_deg[i];
    }
    if (t == 0) g_rowptr[NN] = sh[1023];
}

__global__ void scatter_kernel(const int* __restrict__ src, const int* __restrict__ dst) {
    int e = blockIdx.x * blockDim.x + threadIdx.x;
    if (e < NE) {
        int p = atomicAdd(&g_cursor[dst[e]], 1);
        g_srcs[p] = src[e];
    }
}

// ---------------- per-dst softmax weights: one warp per dst node ----------------
__global__ void alpha_kernel(const float* __restrict__ el, const float* __restrict__ er,
                             float* __restrict__ alpha, float* __restrict__ invp) {
    const int d = blockIdx.x * 8 + (threadIdx.x >> 5);
    if (d >= NN) return;
    const int lane = threadIdx.x & 31;
    const int beg = g_rowptr[d];
    const int end = g_rowptr[d + 1];

    const float4 erd = reinterpret_cast<const float4*>(er)[d];

    float4 m = make_float4(-1e30f, -1e30f, -1e30f, -1e30f);
    for (int e = beg + lane; e < end; e += 32) {
        int sn = g_srcs[e];
        float4 l = reinterpret_cast<const float4*>(el)[sn];
        float4 v;
        v.x = lrelu(l.x + erd.x);
        v.y = lrelu(l.y + erd.y);
        v.z = lrelu(l.z + erd.z);
        v.w = lrelu(l.w + erd.w);
        reinterpret_cast<float4*>(alpha)[e] = v;
        m.x = fmaxf(m.x, v.x); m.y = fmaxf(m.y, v.y);
        m.z = fmaxf(m.z, v.z); m.w = fmaxf(m.w, v.w);
    }
#pragma unroll
    for (int o = 16; o; o >>= 1) {
        m.x = fmaxf(m.x, __shfl_xor_sync(0xffffffffu, m.x, o));
        m.y = fmaxf(m.y, __shfl_xor_sync(0xffffffffu, m.y, o));
        m.z = fmaxf(m.z, __shfl_xor_sync(0xffffffffu, m.z, o));
        m.w = fmaxf(m.w, __shfl_xor_sync(0xffffffffu, m.w, o));
    }

    float4 s = make_float4(0.f, 0.f, 0.f, 0.f);
    for (int e = beg + lane; e < end; e += 32) {
        float4 v = reinterpret_cast<float4*>(alpha)[e];
        v.x = __expf(v.x - m.x); v.y = __expf(v.y - m.y);
        v.z = __expf(v.z - m.z); v.w = __expf(v.w - m.w);
        reinterpret_cast<float4*>(alpha)[e] = v;
        s.x += v.x; s.y += v.y; s.z += v.z; s.w += v.w;
    }
#pragma unroll
    for (int o = 16; o; o >>= 1) {
        s.x += __shfl_xor_sync(0xffffffffu, s.x, o);
        s.y += __shfl_xor_sync(0xffffffffu, s.y, o);
        s.z += __shfl_xor_sync(0xffffffffu, s.z, o);
        s.w += __shfl_xor_sync(0xffffffffu, s.w, o);
    }
    if (lane == 0) {
        float4 inv;
        inv.x = 1.f / (s.x + 1e-9f); inv.y = 1.f / (s.y + 1e-9f);
        inv.z = 1.f / (s.z + 1e-9f); inv.w = 1.f / (s.w + 1e-9f);
        reinterpret_cast<float4*>(invp)[d] = inv;
    }
}

// ---------------- aggregation (fp16 gather); OUT_HALF: write fp16 (feeds GEMM2) ----------------
template <int DH, bool ACT, bool OUT_HALF>
__global__ void aggregate_kernel(const __half* __restrict__ projh,
                                 const float* __restrict__ alpha,
                                 const float* __restrict__ invp,
                                 const float* __restrict__ bias, void* __restrict__ outp) {
    constexpr int C4 = DH;
    const int d = blockIdx.x;
    const int t = threadIdx.x;
    const int beg = g_rowptr[d];
    const int end = g_rowptr[d + 1];
    if (t >= C4) return;

    const int head = (4 * t) / DH;
    const float4 invv = reinterpret_cast<const float4*>(invp)[d];
    const float inv = (head == 0) ? invv.x : (head == 1) ? invv.y : (head == 2) ? invv.z : invv.w;

    float4 acc = make_float4(0.f, 0.f, 0.f, 0.f);
#pragma unroll 2
    for (int e = beg; e < end; e++) {
        int sn = g_srcs[e];
        float4 a = reinterpret_cast<const float4*>(alpha)[e];   // broadcast
        float w = (head == 0) ? a.x : (head == 1) ? a.y : (head == 2) ? a.z : a.w;
        const __half2* ph =
            reinterpret_cast<const __half2*>(projh + (size_t)sn * (4 * DH)) + 2 * t;
        float2 p0 = __half22float2(ph[0]);
        float2 p1 = __half22float2(ph[1]);
        acc.x = fmaf(w, p0.x, acc.x);
        acc.y = fmaf(w, p0.y, acc.y);
        acc.z = fmaf(w, p1.x, acc.z);
        acc.w = fmaf(w, p1.y, acc.w);
    }
    float4 b = reinterpret_cast<const float4*>(bias)[t];
    acc.x = fmaf(acc.x, inv, b.x);
    acc.y = fmaf(acc.y, inv, b.y);
    acc.z = fmaf(acc.z, inv, b.z);
    acc.w = fmaf(acc.w, inv, b.w);
    if (ACT) {
        acc.x = lrelu(acc.x); acc.y = lrelu(acc.y);
        acc.z = lrelu(acc.z); acc.w = lrelu(acc.w);
    }
    if (OUT_HALF) {
        __half2* o = reinterpret_cast<__half2*>((__half*)outp + (size_t)d * (4 * DH)) + 2 * t;
        o[0] = __floats2half2_rn(acc.x, acc.y);
        o[1] = __floats2half2_rn(acc.z, acc.w);
    } else {
        reinterpret_cast<float4*>((float*)outp)[(size_t)d * C4 + t] = acc;
    }
}

// ---------------- launch ----------------
extern "C" void kernel_launch(void* const* d_in, const int* in_sizes, int n_in,
                              void* d_out, int out_size) {
    const float* x   = (const float*)d_in[0];
    const float* W1  = (const float*)d_in[1];
    const float* al1 = (const float*)d_in[2];
    const float* ar1 = (const float*)d_in[3];
    const float* b1  = (const float*)d_in[4];
    const float* W2  = (const float*)d_in[5];
    const float* al2 = (const float*)d_in[6];
    const float* ar2 = (const float*)d_in[7];
    const float* b2  = (const float*)d_in[8];
    const int*   src = (const int*)d_in[9];
    const int*   dst = (const int*)d_in[10];
    float* out = (float*)d_out;

    float *el1, *er1, *el2, *er2, *alpha, *invp, *degp, *wl1, *wl2;
    __half *projh1, *projh2, *xh, *w1h, *w2h, *h1h;
    cudaGetSymbolAddress((void**)&projh1, g_projh1);
    cudaGetSymbolAddress((void**)&projh2, g_projh2);
    cudaGetSymbolAddress((void**)&xh, g_xh);
    cudaGetSymbolAddress((void**)&w1h, g_w1h);
    cudaGetSymbolAddress((void**)&w2h, g_w2h);
    cudaGetSymbolAddress((void**)&h1h, g_h1h);
    cudaGetSymbolAddress((void**)&wl1, g_wl1);
    cudaGetSymbolAddress((void**)&wl2, g_wl2);
    cudaGetSymbolAddress((void**)&el1, g_el1);
    cudaGetSymbolAddress((void**)&er1, g_er1);
    cudaGetSymbolAddress((void**)&el2, g_el2);
    cudaGetSymbolAddress((void**)&er2, g_er2);
    cudaGetSymbolAddress((void**)&alpha, g_alpha);
    cudaGetSymbolAddress((void**)&invp, g_inv);
    cudaGetSymbolAddress((void**)&degp, g_deg);

    // fp32 -> fp16 conversions (RN) + folded score weights
    f2h_pad_kernel<<<(NN * 75 + 255) / 256, 256>>>(x, xh);
    f2h_kernel<<<(300 * 400 / 4 + 255) / 256, 256>>>(W1, w1h, 300 * 400 / 4);
    f2h_kernel<<<(400 * 512 / 4 + 255) / 256, 256>>>(W2, w2h, 400 * 512 / 4);
    make_wl_kernel<300, 100><<<(300 * 8 + 255) / 256, 256>>>(W1, al1, ar1, wl1);
    make_wl_kernel<400, 128><<<(400 * 8 + 255) / 256, 256>>>(W2, al2, ar2, wl2);

    // CSR build
    cudaMemsetAsync(degp, 0, NN * sizeof(int));
    count_deg_kernel<<<(NE + 255) / 256, 256>>>(dst);
    scan_kernel<<<1, 1024>>>();
    scatter_kernel<<<(NE + 255) / 256, 256>>>(src, dst);

    const int ABLK = (NN + 7) / 8;
    const int SBLK = (NN + 7) / 8;
    const int GR = (NN + GBM - 1) / GBM;

    // layer 1
    scores_w_kernel<300, float><<<SBLK, 256>>>(x, 300, wl1, el1, er1);
    {
        dim3 grid((400 + GBN - 1) / GBN, GR);
        gemm_f16<<<grid, 256>>>(xh, w1h, projh1, NN, 400, 300, XLD);
    }
    alpha_kernel<<<ABLK, 256>>>(el1, er1, alpha, invp);
    aggregate_kernel<100, true, true><<<NN, 128>>>(projh1, alpha, invp, b1, h1h);

    // layer 2
    scores_w_kernel<400, __half><<<SBLK, 256>>>(h1h, 400, wl2, el2, er2);
    {
        dim3 grid((512 + GBN - 1) / GBN, GR);
        gemm_f16<<<grid, 256>>>(h1h, w2h, projh2, NN, 512, 400, 400);
    }
    alpha_kernel<<<ABLK, 256>>>(el2, er2, alpha, invp);
    aggregate_kernel<128, false, false><<<NN, 128>>>(projh2, alpha, invp, b2, out);
}

// round 13
// speedup vs baseline: 3.5613x; 1.0693x over previous
#include <cuda_runtime.h>
#include <cuda_fp16.h>
#include <mma.h>
#include <math.h>

using namespace nvcuda;

#define NN 50000
#define NE 800000
#define NHEADS 4
#define SLOPE 0.2f
#define XLD 304              // padded fp16 row stride for x (608B, 16B-aligned)

// ---------------- scratch (static device globals; no allocation) ----------------
__device__ __half g_projh1[NN * 400];      // 40 MB
__device__ __half g_projh2[NN * 512];      // 51.2 MB
__device__ __half g_xh[NN * XLD];          // 30.4 MB (pad cols stay 0)
__device__ __half g_w1h[300 * 400];
__device__ __half g_w2h[400 * 512];
__device__ __half g_h1h[NN * 400];         // 40 MB
__device__ float  g_wl1[300 * 8];
__device__ float  g_wl2[400 * 8];
__device__ float  g_el1[NN * NHEADS];
__device__ float  g_er1[NN * NHEADS];
__device__ float  g_el2[NN * NHEADS];
__device__ float  g_er2[NN * NHEADS];
__device__ float  g_alpha[NE * 4];
__device__ float  g_inv[NN * 4];
__device__ int    g_deg[NN];
__device__ int    g_rowptr[NN + 1];
__device__ int    g_cursor[NN];
__device__ int    g_srcs[NE];

__device__ __forceinline__ float lrelu(float x) { return x > 0.f ? x : SLOPE * x; }

// ---------------- FUSED setup: x-pad f2h | W1 f2h | W2 f2h | wl1 | wl2 | deg count ----------------
#define N_XPAD (NN * 75)
#define N_W1Q  (300 * 400 / 4)
#define N_W2Q  (400 * 512 / 4)
#define N_WL1  (300 * 8)
#define N_WL2  (400 * 8)
#define SETUP_TOTAL (N_XPAD + N_W1Q + N_W2Q + N_WL1 + N_WL2 + NE)

__device__ __forceinline__ void f2h_quad(const float* in, __half* out, int q) {
    float4 v = reinterpret_cast<const float4*>(in)[q];
    reinterpret_cast<__half2*>(out)[2 * q]     = __floats2half2_rn(v.x, v.y);
    reinterpret_cast<__half2*>(out)[2 * q + 1] = __floats2half2_rn(v.z, v.w);
}

__device__ __forceinline__ void make_wl_one(const float* W, const float* al, const float* ar,
                                            float* Wl, int idx, int DH) {
    int k = idx >> 3, j = idx & 7;
    const float* av = (j < 4) ? (al + j * DH) : (ar + (j - 4) * DH);
    const float* wrow = W + (size_t)k * (4 * DH) + (j & 3) * DH;
    float s = 0.f;
    for (int d = 0; d < DH; d++) s = fmaf(wrow[d], av[d], s);
    Wl[idx] = s;
}

__global__ void setup_kernel(const float* __restrict__ x,
                             const float* __restrict__ W1, const float* __restrict__ al1, const float* __restrict__ ar1,
                             const float* __restrict__ W2, const float* __restrict__ al2, const float* __restrict__ ar2,
                             const int* __restrict__ dst) {
    int i = blockIdx.x * blockDim.x + threadIdx.x;
    if (i < N_XPAD) {
        int row = i / 75, q = i % 75;
        float4 v = *reinterpret_cast<const float4*>(x + (size_t)row * 300 + q * 4);
        __half* o = g_xh + (size_t)row * XLD + q * 4;
        reinterpret_cast<__half2*>(o)[0] = __floats2half2_rn(v.x, v.y);
        reinterpret_cast<__half2*>(o)[1] = __floats2half2_rn(v.z, v.w);
        return;
    }
    i -= N_XPAD;
    if (i < N_W1Q) { f2h_quad(W1, g_w1h, i); return; }
    i -= N_W1Q;
    if (i < N_W2Q) { f2h_quad(W2, g_w2h, i); return; }
    i -= N_W2Q;
    if (i < N_WL1) { make_wl_one(W1, al1, ar1, g_wl1, i, 100); return; }
    i -= N_WL1;
    if (i < N_WL2) { make_wl_one(W2, al2, ar2, g_wl2, i, 128); return; }
    i -= N_WL2;
    if (i < NE) atomicAdd(&g_deg[dst[i]], 1);
}

// ---------------- scores via folded Wl: one warp per node ----------------
template <int K, typename T>
__global__ void scores_w_kernel(const T* __restrict__ X, int ldx,
                                const float* __restrict__ Wl,
                                float* __restrict__ el, float* __restrict__ er) {
    __shared__ float sw[K][9];
    const int tid = threadIdx.x;
    for (int i = tid; i < K * 8; i += 256) sw[i >> 3][i & 7] = Wl[i];
    __syncthreads();
    const int warp = tid >> 5, lane = tid & 31;
    const int n = blockIdx.x * 8 + warp;
    if (n >= NN) return;
    const T* xrow = X + (size_t)n * ldx;
    float a[8] = {0.f, 0.f, 0.f, 0.f, 0.f, 0.f, 0.f, 0.f};
    for (int k = lane; k < K; k += 32) {
        float xv = (float)xrow[k];
#pragma unroll
        for (int j = 0; j < 8; j++) a[j] = fmaf(xv, sw[k][j], a[j]);
    }
#pragma unroll
    for (int j = 0; j < 8; j++)
#pragma unroll
        for (int o = 16; o; o >>= 1) a[j] += __shfl_xor_sync(0xffffffffu, a[j], o);
    if (lane == 0) {
        reinterpret_cast<float4*>(el)[n] = make_float4(a[0], a[1], a[2], a[3]);
        reinterpret_cast<float4*>(er)[n] = make_float4(a[4], a[5], a[6], a[7]);
    }
}

// ---------------- cp.async helpers ----------------
__device__ __forceinline__ void cp_async16(void* smem, const void* g) {
    unsigned saddr = (unsigned)__cvta_generic_to_shared(smem);
    asm volatile("cp.async.cg.shared.global [%0], [%1], 16;\n" :: "r"(saddr), "l"(g));
}
__device__ __forceinline__ void cp_commit() { asm volatile("cp.async.commit_group;\n" ::: "memory"); }
__device__ __forceinline__ void cp_wait0()  { asm volatile("cp.async.wait_group 0;\n" ::: "memory"); }
__device__ __forceinline__ void cp_wait1()  { asm volatile("cp.async.wait_group 1;\n" ::: "memory"); }

// ---------------- FP16 WMMA GEMM (fp32 accumulate), 3-stage cp.async, dynamic smem ----------------
// 8 warps: 2 (M, x64) x 4 (N, x 16*WNF). WNF = GBN/64 (1 or 2).
#define GBM 128
#define GBK 32
#define LDA 40

template <int GBN>
__global__ void __launch_bounds__(256, 2)
gemm_f16(const __half* __restrict__ A, const __half* __restrict__ B,
         __half* __restrict__ Ch, int M, int N, int K, int lda) {
    constexpr int WNF = GBN / 64;
    constexpr int WNT = 16 * WNF;
    constexpr int LDB = GBN + 8;
    constexpr int LDC = GBN + 4;
    constexpr int ABUF = GBM * LDA;
    constexpr int BBUF = GBK * LDB;
    constexpr int TILEBUF = ABUF + BBUF;

    extern __shared__ __align__(16) char smem_raw[];
    __half* sbuf = reinterpret_cast<__half*>(smem_raw);

    const int tid  = threadIdx.x;
    const int warp = tid >> 5;
    const int wm   = warp & 1;
    const int wn   = warp >> 1;
    const int bm   = blockIdx.y * GBM;
    const int bn   = blockIdx.x * GBN;

    wmma::fragment<wmma::accumulator, 16, 16, 16, float> acc[4][WNF];
#pragma unroll
    for (int i = 0; i < 4; i++)
#pragma unroll
        for (int j = 0; j < WNF; j++) wmma::fill_fragment(acc[i][j], 0.f);

    auto load_tile = [&](int buf, int kt) {
        __half* As = sbuf + buf * TILEBUF;
        __half* Bs = As + ABUF;
#pragma unroll
        for (int it = 0; it < 2; it++) {
            int s = tid + 256 * it;
            int r = s >> 2, c8 = s & 3;
            int gr = bm + r, gc = kt + c8 * 8;
            __half* dstp = &As[r * LDA + c8 * 8];
            if (gr < M && gc < K) cp_async16(dstp, A + (size_t)gr * lda + gc);
            else *reinterpret_cast<float4*>(dstp) = make_float4(0.f, 0.f, 0.f, 0.f);
        }
        constexpr int BCH = GBK * GBN / 8;   // 8-half chunks
#pragma unroll
        for (int s = 0; s < BCH; s += 256) {
            int sl = s + tid;
            int r = sl / (GBN / 8), c8 = sl % (GBN / 8);
            int gr = kt + r, gc = bn + c8 * 8;
            __half* dstp = &Bs[r * LDB + c8 * 8];
            if (gr < K && gc < N) cp_async16(dstp, B + (size_t)gr * N + gc);
            else *reinterpret_cast<float4*>(dstp) = make_float4(0.f, 0.f, 0.f, 0.f);
        }
        cp_commit();
    };

    load_tile(0, 0);
    if (GBK < K) load_tile(1, GBK);

    int buf = 0;
    for (int kt = 0; kt < K; kt += GBK) {
        if (kt + GBK < K) cp_wait1(); else cp_wait0();
        __syncthreads();
        if (kt + 2 * GBK < K) load_tile((buf + 2) % 3, kt + 2 * GBK);

        const __half* As = sbuf + buf * TILEBUF;
        const __half* Bs = As + ABUF;
#pragma unroll
        for (int ks = 0; ks < GBK; ks += 16) {
            wmma::fragment<wmma::matrix_a, 16, 16, 16, __half, wmma::row_major> af[4];
            wmma::fragment<wmma::matrix_b, 16, 16, 16, __half, wmma::row_major> bf[WNF];
#pragma unroll
            for (int i = 0; i < 4; i++)
                wmma::load_matrix_sync(af[i], &As[(wm * 64 + i * 16) * LDA + ks], LDA);
#pragma unroll
            for (int j = 0; j < WNF; j++)
                wmma::load_matrix_sync(bf[j], &Bs[ks * LDB + wn * WNT + j * 16], LDB);
#pragma unroll
            for (int i = 0; i < 4; i++)
#pragma unroll
                for (int j = 0; j < WNF; j++)
                    wmma::mma_sync(acc[i][j], af[i], bf[j], acc[i][j]);
        }
        buf = (buf + 1) % 3;
        __syncthreads();
    }

    // ---- epilogue: two 64-row halves through float staging; fp16-only output ----
    float* CS = reinterpret_cast<float*>(smem_raw);
#pragma unroll
    for (int half = 0; half < 2; half++) {
        if (wm == half) {
#pragma unroll
            for (int i = 0; i < 4; i++)
#pragma unroll
                for (int j = 0; j < WNF; j++)
                    wmma::store_matrix_sync(&CS[(i * 16) * LDC + wn * WNT + j * 16],
                                            acc[i][j], LDC, wmma::mem_row_major);
        }
        __syncthreads();
        constexpr int OS = 16 * GBN;   // float4 slots in half
#pragma unroll
        for (int s = 0; s < OS; s += 256) {
            int sl = s + tid;
            int r = sl / (GBN / 4), c4 = sl % (GBN / 4);
            int gr = bm + half * 64 + r, gc = bn + c4 * 4;
            if (gr < M && gc < N) {
                float4 v = *reinterpret_cast<float4*>(&CS[r * LDC + c4 * 4]);
                *reinterpret_cast<__half2*>(Ch + (size_t)gr * N + gc)     = __floats2half2_rn(v.x, v.y);
                *reinterpret_cast<__half2*>(Ch + (size_t)gr * N + gc + 2) = __floats2half2_rn(v.z, v.w);
            }
        }
        __syncthreads();
    }
}

// ---------------- CSR scan + scatter ----------------
__global__ void scan_kernel() {
    __shared__ int sh[1024];
    const int t = threadIdx.x;
    const int CHUNK = (NN + 1023) / 1024;
    int beg = t * CHUNK;
    int end = min(beg + CHUNK, NN);
    int s = 0;
    for (int i = beg; i < end; i++) s += g_deg[i];
    sh[t] = s;
    __syncthreads();
    for (int off = 1; off < 1024; off <<= 1) {
        int v = (t >= off) ? sh[t - off] : 0;
        __syncthreads();
        sh[t] += v;
        __syncthreads();
    }
    int run = t ? sh[t - 1] : 0;
    for (int i = beg; i < end; i++) {
        g_rowptr[i] = run;
        g_cursor[i] = run;
        run += g_deg[i];
    }
    if (t == 0) g_rowptr[NN] = sh[1023];
}

__global__ void scatter_kernel(const int* __restrict__ src, const int* __restrict__ dst) {
    int e = blockIdx.x * blockDim.x + threadIdx.x;
    if (e < NE) {
        int p = atomicAdd(&g_cursor[dst[e]], 1);
        g_srcs[p] = src[e];
    }
}

// ---------------- per-dst softmax weights: one warp per dst node ----------------
__global__ void alpha_kernel(const float* __restrict__ el, const float* __restrict__ er,
                             float* __restrict__ alpha, float* __restrict__ invp) {
    const int d = blockIdx.x * 8 + (threadIdx.x >> 5);
    if (d >= NN) return;
    const int lane = threadIdx.x & 31;
    const int beg = g_rowptr[d];
    const int end = g_rowptr[d + 1];

    const float4 erd = reinterpret_cast<const float4*>(er)[d];

    float4 m = make_float4(-1e30f, -1e30f, -1e30f, -1e30f);
    for (int e = beg + lane; e < end; e += 32) {
        int sn = g_srcs[e];
        float4 l = reinterpret_cast<const float4*>(el)[sn];
        float4 v;
        v.x = lrelu(l.x + erd.x);
        v.y = lrelu(l.y + erd.y);
        v.z = lrelu(l.z + erd.z);
        v.w = lrelu(l.w + erd.w);
        reinterpret_cast<float4*>(alpha)[e] = v;
        m.x = fmaxf(m.x, v.x); m.y = fmaxf(m.y, v.y);
        m.z = fmaxf(m.z, v.z); m.w = fmaxf(m.w, v.w);
    }
#pragma unroll
    for (int o = 16; o; o >>= 1) {
        m.x = fmaxf(m.x, __shfl_xor_sync(0xffffffffu, m.x, o));
        m.y = fmaxf(m.y, __shfl_xor_sync(0xffffffffu, m.y, o));
        m.z = fmaxf(m.z, __shfl_xor_sync(0xffffffffu, m.z, o));
        m.w = fmaxf(m.w, __shfl_xor_sync(0xffffffffu, m.w, o));
    }

    float4 s = make_float4(0.f, 0.f, 0.f, 0.f);
    for (int e = beg + lane; e < end; e += 32) {
        float4 v = reinterpret_cast<float4*>(alpha)[e];
        v.x = __expf(v.x - m.x); v.y = __expf(v.y - m.y);
        v.z = __expf(v.z - m.z); v.w = __expf(v.w - m.w);
        reinterpret_cast<float4*>(alpha)[e] = v;
        s.x += v.x; s.y += v.y; s.z += v.z; s.w += v.w;
    }
#pragma unroll
    for (int o = 16; o; o >>= 1) {
        s.x += __shfl_xor_sync(0xffffffffu, s.x, o);
        s.y += __shfl_xor_sync(0xffffffffu, s.y, o);
        s.z += __shfl_xor_sync(0xffffffffu, s.z, o);
        s.w += __shfl_xor_sync(0xffffffffu, s.w, o);
    }
    if (lane == 0) {
        float4 inv;
        inv.x = 1.f / (s.x + 1e-9f); inv.y = 1.f / (s.y + 1e-9f);
        inv.z = 1.f / (s.z + 1e-9f); inv.w = 1.f / (s.w + 1e-9f);
        reinterpret_cast<float4*>(invp)[d] = inv;
    }
}

// ---------------- aggregation (fp16 gather); OUT_HALF: write fp16 (feeds GEMM2) ----------------
template <int DH, bool ACT, bool OUT_HALF>
__global__ void aggregate_kernel(const __half* __restrict__ projh,
                                 const float* __restrict__ alpha,
                                 const float* __restrict__ invp,
                                 const float* __restrict__ bias, void* __restrict__ outp) {
    constexpr int C4 = DH;
    const int d = blockIdx.x;
    const int t = threadIdx.x;
    const int beg = g_rowptr[d];
    const int end = g_rowptr[d + 1];
    if (t >= C4) return;

    const int head = (4 * t) / DH;
    const float4 invv = reinterpret_cast<const float4*>(invp)[d];
    const float inv = (head == 0) ? invv.x : (head == 1) ? invv.y : (head == 2) ? invv.z : invv.w;

    float4 acc = make_float4(0.f, 0.f, 0.f, 0.f);
#pragma unroll 2
    for (int e = beg; e < end; e++) {
        int sn = g_srcs[e];
        float4 a = reinterpret_cast<const float4*>(alpha)[e];   // broadcast
        float w = (head == 0) ? a.x : (head == 1) ? a.y : (head == 2) ? a.z : a.w;
        const __half2* ph =
            reinterpret_cast<const __half2*>(projh + (size_t)sn * (4 * DH)) + 2 * t;
        float2 p0 = __half22float2(ph[0]);
        float2 p1 = __half22float2(ph[1]);
        acc.x = fmaf(w, p0.x, acc.x);
        acc.y = fmaf(w, p0.y, acc.y);
        acc.z = fmaf(w, p1.x, acc.z);
        acc.w = fmaf(w, p1.y, acc.w);
    }
    float4 b = reinterpret_cast<const float4*>(bias)[t];
    acc.x = fmaf(acc.x, inv, b.x);
    acc.y = fmaf(acc.y, inv, b.y);
    acc.z = fmaf(acc.z, inv, b.z);
    acc.w = fmaf(acc.w, inv, b.w);
    if (ACT) {
        acc.x = lrelu(acc.x); acc.y = lrelu(acc.y);
        acc.z = lrelu(acc.z); acc.w = lrelu(acc.w);
    }
    if (OUT_HALF) {
        __half2* o = reinterpret_cast<__half2*>((__half*)outp + (size_t)d * (4 * DH)) + 2 * t;
        o[0] = __floats2half2_rn(acc.x, acc.y);
        o[1] = __floats2half2_rn(acc.z, acc.w);
    } else {
        reinterpret_cast<float4*>((float*)outp)[(size_t)d * C4 + t] = acc;
    }
}

// ---------------- launch ----------------
extern "C" void kernel_launch(void* const* d_in, const int* in_sizes, int n_in,
                              void* d_out, int out_size) {
    const float* x   = (const float*)d_in[0];
    const float* W1  = (const float*)d_in[1];
    const float* al1 = (const float*)d_in[2];
    const float* ar1 = (const float*)d_in[3];
    const float* b1  = (const float*)d_in[4];
    const float* W2  = (const float*)d_in[5];
    const float* al2 = (const float*)d_in[6];
    const float* ar2 = (const float*)d_in[7];
    const float* b2  = (const float*)d_in[8];
    const int*   src = (const int*)d_in[9];
    const int*   dst = (const int*)d_in[10];
    float* out = (float*)d_out;

    float *el1, *er1, *el2, *er2, *alpha, *invp, *degp, *wl1, *wl2;
    __half *projh1, *projh2, *xh, *w1h, *w2h, *h1h;
    cudaGetSymbolAddress((void**)&projh1, g_projh1);
    cudaGetSymbolAddress((void**)&projh2, g_projh2);
    cudaGetSymbolAddress((void**)&xh, g_xh);
    cudaGetSymbolAddress((void**)&w1h, g_w1h);
    cudaGetSymbolAddress((void**)&w2h, g_w2h);
    cudaGetSymbolAddress((void**)&h1h, g_h1h);
    cudaGetSymbolAddress((void**)&wl1, g_wl1);
    cudaGetSymbolAddress((void**)&wl2, g_wl2);
    cudaGetSymbolAddress((void**)&el1, g_el1);
    cudaGetSymbolAddress((void**)&er1, g_er1);
    cudaGetSymbolAddress((void**)&el2, g_el2);
    cudaGetSymbolAddress((void**)&er2, g_er2);
    cudaGetSymbolAddress((void**)&alpha, g_alpha);
    cudaGetSymbolAddress((void**)&invp, g_inv);
    cudaGetSymbolAddress((void**)&degp, g_deg);

    // opt-in dynamic smem for the GEMMs
    constexpr int SMEM64  = 3 * (GBM * LDA + GBK * (64 + 8)) * 2;    // 44544
    constexpr int SMEM128 = 3 * (GBM * LDA + GBK * (128 + 8)) * 2;   // 56832
    cudaFuncSetAttribute(gemm_f16<64>,  cudaFuncAttributeMaxDynamicSharedMemorySize, SMEM64);
    cudaFuncSetAttribute(gemm_f16<128>, cudaFuncAttributeMaxDynamicSharedMemorySize, SMEM128);

    // fused setup (conversions + Wl folds + degree count); deg must be zeroed first
    cudaMemsetAsync(degp, 0, NN * sizeof(int));
    setup_kernel<<<(SETUP_TOTAL + 255) / 256, 256>>>(x, W1, al1, ar1, W2, al2, ar2, dst);
    scan_kernel<<<1, 1024>>>();
    scatter_kernel<<<(NE + 255) / 256, 256>>>(src, dst);

    const int ABLK = (NN + 7) / 8;
    const int GR = (NN + GBM - 1) / GBM;

    // layer 1
    scores_w_kernel<300, float><<<ABLK, 256>>>(x, 300, wl1, el1, er1);
    {
        dim3 grid((400 + 63) / 64, GR);
        gemm_f16<64><<<grid, 256, SMEM64>>>(xh, w1h, projh1, NN, 400, 300, XLD);
    }
    alpha_kernel<<<ABLK, 256>>>(el1, er1, alpha, invp);
    aggregate_kernel<100, true, true><<<NN, 128>>>(projh1, alpha, invp, b1, h1h);

    // layer 2
    scores_w_kernel<400, __half><<<ABLK, 256>>>(h1h, 400, wl2, el2, er2);
    {
        dim3 grid(512 / 128, GR);
        gemm_f16<128><<<grid, 256, SMEM128>>>(h1h, w2h, projh2, NN, 512, 400, 400);
    }
    alpha_kernel<<<ABLK, 256>>>(el2, er2, alpha, invp);
    aggregate_kernel<128, false, false><<<NN, 128>>>(projh2, alpha, invp, b2, out);
}